// round 1
// baseline (speedup 1.0000x reference)
#include <cuda_runtime.h>
#include <math.h>

// ---------------- problem constants ----------------
#define B_   2
#define T_   2048
#define D_   2048
#define H_   16
#define HKV_ 4
#define HD_  128
#define DKV_ (HKV_*HD_)   // 512
#define MROWS (B_*T_)     // 4096
#define LOG2E 1.4426950408889634f

// ---------------- scratch (device globals: no allocation allowed) ----------------
__device__ float g_q_tmp[(size_t)MROWS * D_];     // pre-RoPE Q (B*T, 2048)
__device__ float g_k_tmp[(size_t)MROWS * DKV_];   // pre-RoPE K (B*T, 512)
__device__ float g_v[(size_t)MROWS * DKV_];       // V (B*T, 512)
__device__ float g_qT[(size_t)B_*H_*HD_*T_];      // Q rotated, (b,h,d,t)
__device__ float g_kT[(size_t)B_*HKV_*HD_*T_];    // K rotated, (b,hkv,d,t)
__device__ float g_attn[(size_t)MROWS * D_];      // attention output (B*T, 2048)
__device__ float g_cos_t[T_*64];
__device__ float g_sin_t[T_*64];

// ---------------- RoPE table (fp64 for accuracy, ~8us) ----------------
__global__ void rope_table_kernel() {
    int t = blockIdx.x;
    int i = threadIdx.x;                       // 0..63
    double inv = exp(-((double)(2*i) / 128.0) * 9.210340371976182736); // ln(10000)
    double ang = (double)t * inv;
    g_cos_t[t*64 + i] = (float)cos(ang);
    g_sin_t[t*64 + i] = (float)sin(ang);
}

// ---------------- SGEMM: C[M,N] = A[M,K] @ B[K,N], all row-major ----------------
// 128x128 block tile, BK=16, 256 threads, 8x8 per-thread register tile.
__global__ __launch_bounds__(256, 2)
void sgemm128(const float* __restrict__ A, const float* __restrict__ B,
              float* __restrict__ C, int M, int N, int K) {
    __shared__ float As[16][132];   // A transposed: As[k][m]
    __shared__ float Bs[16][132];   // Bs[k][n]
    int tid = threadIdx.x;
    int tx = tid & 15, ty = tid >> 4;
    int row0 = blockIdx.y << 7;
    int col0 = blockIdx.x << 7;

    float acc[8][8];
#pragma unroll
    for (int i = 0; i < 8; ++i)
#pragma unroll
        for (int j = 0; j < 8; ++j) acc[i][j] = 0.f;

    for (int k0 = 0; k0 < K; k0 += 16) {
        // load A tile (128 x 16) -> transposed smem
#pragma unroll
        for (int e = tid; e < 512; e += 256) {
            int r  = e >> 2;
            int k4 = (e & 3) << 2;
            float4 va = *(const float4*)(A + (size_t)(row0 + r)*K + k0 + k4);
            As[k4+0][r] = va.x; As[k4+1][r] = va.y;
            As[k4+2][r] = va.z; As[k4+3][r] = va.w;
        }
        // load B tile (16 x 128)
#pragma unroll
        for (int e = tid; e < 512; e += 256) {
            int r  = e >> 5;
            int n4 = (e & 31) << 2;
            *(float4*)&Bs[r][n4] = *(const float4*)(B + (size_t)(k0 + r)*N + col0 + n4);
        }
        __syncthreads();
#pragma unroll
        for (int kk = 0; kk < 16; ++kk) {
            float4 a0 = *(float4*)&As[kk][8*ty];
            float4 a1 = *(float4*)&As[kk][8*ty+4];
            float4 b0 = *(float4*)&Bs[kk][8*tx];
            float4 b1 = *(float4*)&Bs[kk][8*tx+4];
            float a[8] = {a0.x,a0.y,a0.z,a0.w,a1.x,a1.y,a1.z,a1.w};
            float b[8] = {b0.x,b0.y,b0.z,b0.w,b1.x,b1.y,b1.z,b1.w};
#pragma unroll
            for (int i = 0; i < 8; ++i)
#pragma unroll
                for (int j = 0; j < 8; ++j) acc[i][j] += a[i]*b[j];
        }
        __syncthreads();
    }
#pragma unroll
    for (int i = 0; i < 8; ++i) {
        float* crow = C + (size_t)(row0 + 8*ty + i)*N + col0 + 8*tx;
        *(float4*)(crow)     = make_float4(acc[i][0], acc[i][1], acc[i][2], acc[i][3]);
        *(float4*)(crow + 4) = make_float4(acc[i][4], acc[i][5], acc[i][6], acc[i][7]);
    }
}

// ---------------- fused RoPE + transpose to (b, head, d, t) ----------------
// in:  (B, T, nheads*128) row-major, per-head slice rotated
// out: (b*nheads+h, d, t) with t contiguous  (row length T_)
__global__ void rope_transpose_kernel(const float* __restrict__ in, float* __restrict__ outT,
                                      int nheads, int rowWidth, float scale) {
    __shared__ float S[32][129];
    int t0 = blockIdx.x << 5;
    int h  = blockIdx.y;
    int b  = blockIdx.z;
    const float* base = in + ((size_t)b*T_ + t0)*rowWidth + h*HD_;
#pragma unroll
    for (int e = threadIdx.x; e < 32*32; e += 256) {
        int t  = e >> 5;
        int d4 = (e & 31) << 2;
        float4 v = *(const float4*)(base + (size_t)t*rowWidth + d4);
        S[t][d4+0] = v.x; S[t][d4+1] = v.y; S[t][d4+2] = v.z; S[t][d4+3] = v.w;
    }
    __syncthreads();
    float* obase = outT + ((size_t)(b*nheads + h)*HD_)*T_ + t0;
#pragma unroll
    for (int e = threadIdx.x; e < 32*128; e += 256) {
        int t  = e & 31;
        int d  = e >> 5;
        int dm = d & 63;
        float c = g_cos_t[(t0 + t)*64 + dm];
        float s = g_sin_t[(t0 + t)*64 + dm];
        float x1 = S[t][d];
        float x2 = (d < 64) ? S[t][d + 64] : S[t][d - 64];
        float val = (d < 64) ? (x1*c - x2*s) : (x1*c + x2*s);
        obase[(size_t)d*T_ + t] = val * scale;
    }
}

// ---------------- causal flash attention (fp32, online softmax) ----------------
// Q tile 64 rows, K tile 64, hd=128. 256 threads = 16x16.
// qT/kT in (bh, d, t) layout (conflict-free transposed smem), V in (b,t,hkv*hd).
#define FA_SMEM_FLOATS (128*68 + 128*68 + 64*132 + 64*68)
__global__ __launch_bounds__(256, 1)
void flash_kernel(const float* __restrict__ qT, const float* __restrict__ kT,
                  const float* __restrict__ v, float* __restrict__ out) {
    extern __shared__ float sm[];
    float* Qt = sm;                     // [128][68]  Qt[d][t]
    float* Kt = Qt + 128*68;            // [128][68]
    float* Vs = Kt + 128*68;            // [64][132]  Vs[t][d]
    float* Ps = Vs + 64*132;            // [64][68]

    int qt = gridDim.x - 1 - blockIdx.x;     // heavy tiles first
    int q0 = qt << 6;
    int bh = blockIdx.y;                     // b*16 + h
    int b  = bh >> 4, h = bh & 15;
    int kvh = h >> 2;
    int tid = threadIdx.x, tx = tid & 15, ty = tid >> 4;

    const float* qbase = qT + (size_t)bh * HD_ * T_;
    const float* kbase = kT + (size_t)(b*HKV_ + kvh) * HD_ * T_;
    const float* vbase = v  + (size_t)b * T_ * DKV_ + kvh*HD_;

    // load Q tile: Qt[d][t], t = 0..63 at q0
#pragma unroll
    for (int e = tid; e < 2048; e += 256) {
        int d  = e >> 4;
        int t4 = (e & 15) << 2;
        *(float4*)&Qt[d*68 + t4] = *(const float4*)(qbase + (size_t)d*T_ + q0 + t4);
    }

    float o[4][8];
    float m[4], l[4];
#pragma unroll
    for (int i = 0; i < 4; ++i) {
        m[i] = -1e30f; l[i] = 0.f;
#pragma unroll
        for (int j = 0; j < 8; ++j) o[i][j] = 0.f;
    }

    for (int kt = 0; kt <= qt; ++kt) {
        int k0 = kt << 6;
        // load K tile transposed + V tile row-major
#pragma unroll
        for (int e = tid; e < 2048; e += 256) {
            int d  = e >> 4;
            int t4 = (e & 15) << 2;
            *(float4*)&Kt[d*68 + t4] = *(const float4*)(kbase + (size_t)d*T_ + k0 + t4);
        }
#pragma unroll
        for (int e = tid; e < 2048; e += 256) {
            int t  = e >> 5;
            int d4 = (e & 31) << 2;
            *(float4*)&Vs[t*132 + d4] = *(const float4*)(vbase + (size_t)(k0 + t)*DKV_ + d4);
        }
        __syncthreads();

        // S = Q K^T  (scale already folded into Q)
        float acc[4][4];
#pragma unroll
        for (int i = 0; i < 4; ++i)
#pragma unroll
            for (int j = 0; j < 4; ++j) acc[i][j] = 0.f;
#pragma unroll 8
        for (int d = 0; d < 128; ++d) {
            float4 qv = *(float4*)&Qt[d*68 + 4*ty];
            float4 kv = *(float4*)&Kt[d*68 + 4*tx];
            acc[0][0] += qv.x*kv.x; acc[0][1] += qv.x*kv.y; acc[0][2] += qv.x*kv.z; acc[0][3] += qv.x*kv.w;
            acc[1][0] += qv.y*kv.x; acc[1][1] += qv.y*kv.y; acc[1][2] += qv.y*kv.z; acc[1][3] += qv.y*kv.w;
            acc[2][0] += qv.z*kv.x; acc[2][1] += qv.z*kv.y; acc[2][2] += qv.z*kv.z; acc[2][3] += qv.z*kv.w;
            acc[3][0] += qv.w*kv.x; acc[3][1] += qv.w*kv.y; acc[3][2] += qv.w*kv.z; acc[3][3] += qv.w*kv.w;
        }

        if (kt == qt) {   // causal mask on diagonal tile (k0 == q0)
#pragma unroll
            for (int i = 0; i < 4; ++i)
#pragma unroll
                for (int j = 0; j < 4; ++j)
                    if (4*tx + j > 4*ty + i) acc[i][j] = -1e30f;
        }

        // online softmax update
#pragma unroll
        for (int i = 0; i < 4; ++i) {
            float tm = fmaxf(fmaxf(acc[i][0], acc[i][1]), fmaxf(acc[i][2], acc[i][3]));
            tm = fmaxf(tm, __shfl_xor_sync(0xffffffffu, tm, 1));
            tm = fmaxf(tm, __shfl_xor_sync(0xffffffffu, tm, 2));
            tm = fmaxf(tm, __shfl_xor_sync(0xffffffffu, tm, 4));
            tm = fmaxf(tm, __shfl_xor_sync(0xffffffffu, tm, 8));
            float mn = fmaxf(m[i], tm);
            float corr = exp2f((m[i] - mn) * LOG2E);
            float rs = 0.f;
#pragma unroll
            for (int j = 0; j < 4; ++j) {
                float p = exp2f((acc[i][j] - mn) * LOG2E);
                acc[i][j] = p;
                rs += p;
            }
            rs += __shfl_xor_sync(0xffffffffu, rs, 1);
            rs += __shfl_xor_sync(0xffffffffu, rs, 2);
            rs += __shfl_xor_sync(0xffffffffu, rs, 4);
            rs += __shfl_xor_sync(0xffffffffu, rs, 8);
            l[i] = l[i] * corr + rs;
            m[i] = mn;
#pragma unroll
            for (int j = 0; j < 8; ++j) o[i][j] *= corr;
            *(float4*)&Ps[(4*ty + i)*68 + 4*tx] =
                make_float4(acc[i][0], acc[i][1], acc[i][2], acc[i][3]);
        }
        __syncthreads();

        // O += P @ V
#pragma unroll 4
        for (int kk = 0; kk < 64; ++kk) {
            float4 v0 = *(float4*)&Vs[kk*132 + 8*tx];
            float4 v1 = *(float4*)&Vs[kk*132 + 8*tx + 4];
#pragma unroll
            for (int i = 0; i < 4; ++i) {
                float p = Ps[(4*ty + i)*68 + kk];
                o[i][0] += p*v0.x; o[i][1] += p*v0.y; o[i][2] += p*v0.z; o[i][3] += p*v0.w;
                o[i][4] += p*v1.x; o[i][5] += p*v1.y; o[i][6] += p*v1.z; o[i][7] += p*v1.w;
            }
        }
        __syncthreads();
    }

    // epilogue: divide by l, write (B, T, H*hd)
#pragma unroll
    for (int i = 0; i < 4; ++i) {
        float inv = 1.f / l[i];
        float* orow = out + (size_t)(b*T_ + q0 + 4*ty + i)*D_ + h*HD_ + 8*tx;
        *(float4*)(orow)     = make_float4(o[i][0]*inv, o[i][1]*inv, o[i][2]*inv, o[i][3]*inv);
        *(float4*)(orow + 4) = make_float4(o[i][4]*inv, o[i][5]*inv, o[i][6]*inv, o[i][7]*inv);
    }
}

// ---------------- launch ----------------
extern "C" void kernel_launch(void* const* d_in, const int* in_sizes, int n_in,
                              void* d_out, int out_size) {
    const float* x  = (const float*)d_in[0];
    const float* Wq = (const float*)d_in[1];
    const float* Wk = (const float*)d_in[2];
    const float* Wv = (const float*)d_in[3];
    const float* Wo = (const float*)d_in[4];
    float* out = (float*)d_out;

    float *qtmp, *ktmp, *vbuf, *qT, *kT, *attn;
    cudaGetSymbolAddress((void**)&qtmp, g_q_tmp);
    cudaGetSymbolAddress((void**)&ktmp, g_k_tmp);
    cudaGetSymbolAddress((void**)&vbuf, g_v);
    cudaGetSymbolAddress((void**)&qT,   g_qT);
    cudaGetSymbolAddress((void**)&kT,   g_kT);
    cudaGetSymbolAddress((void**)&attn, g_attn);

    // RoPE cos/sin table (fp64 precompute, deterministic every call)
    rope_table_kernel<<<T_, 64>>>();

    // projections
    sgemm128<<<dim3(D_/128,   MROWS/128), 256>>>(x, Wq, qtmp, MROWS, D_,   D_);
    sgemm128<<<dim3(DKV_/128, MROWS/128), 256>>>(x, Wk, ktmp, MROWS, DKV_, D_);
    sgemm128<<<dim3(DKV_/128, MROWS/128), 256>>>(x, Wv, vbuf, MROWS, DKV_, D_);

    // RoPE + transpose (scale 1/sqrt(hd) folded into Q)
    rope_transpose_kernel<<<dim3(T_/32, H_,   B_), 256>>>(qtmp, qT, H_,   D_,   0.08838834764831845f);
    rope_transpose_kernel<<<dim3(T_/32, HKV_, B_), 256>>>(ktmp, kT, HKV_, DKV_, 1.0f);

    // flash attention
    static const int fa_smem = FA_SMEM_FLOATS * (int)sizeof(float);
    cudaFuncSetAttribute(flash_kernel, cudaFuncAttributeMaxDynamicSharedMemorySize, fa_smem);
    flash_kernel<<<dim3(T_/64, B_*H_), 256, fa_smem>>>(qT, kT, vbuf, attn);

    // output projection
    sgemm128<<<dim3(D_/128, MROWS/128), 256>>>(attn, Wo, out, MROWS, D_, D_);
}

// round 2
// speedup vs baseline: 1.7252x; 1.7252x over previous
#include <cuda_runtime.h>
#include <math.h>
#include <stdint.h>

// ---------------- problem constants ----------------
#define B_   2
#define T_   2048
#define D_   2048
#define H_   16
#define HKV_ 4
#define HD_  128
#define DKV_ (HKV_*HD_)   // 512
#define MROWS (B_*T_)     // 4096
#define LOG2E 1.4426950408889634f

// ---------------- scratch (device globals: no allocation allowed) ----------------
__device__ float g_q_tmp[(size_t)MROWS * D_];     // pre-RoPE Q
__device__ float g_k_tmp[(size_t)MROWS * DKV_];   // pre-RoPE K
__device__ float g_v[(size_t)MROWS * DKV_];       // V
__device__ float g_qT[(size_t)B_*H_*HD_*T_];      // Q rotated, (b,h,d,t)
__device__ float g_kT[(size_t)B_*HKV_*HD_*T_];    // K rotated, (b,hkv,d,t)
__device__ float g_attn[(size_t)MROWS * D_];      // attention output (tf32-rounded)
__device__ float g_cos_t[T_*64];
__device__ float g_sin_t[T_*64];
// tf32-rounded operand copies (unbiased rna rounding done once, outside GEMM loop)
__device__ float g_xr [(size_t)MROWS * D_];
__device__ float g_wqr[(size_t)D_ * D_];
__device__ float g_wkr[(size_t)D_ * DKV_];
__device__ float g_wvr[(size_t)D_ * DKV_];
__device__ float g_wor[(size_t)D_ * D_];

// ---------------- helpers ----------------
__device__ __forceinline__ float tf32r(float x) {
    uint32_t u;
    asm("cvt.rna.tf32.f32 %0, %1;" : "=r"(u) : "f"(x));
    return __uint_as_float(u);
}
__device__ __forceinline__ uint32_t smem_u32(const void* p) {
    return (uint32_t)__cvta_generic_to_shared(p);
}
__device__ __forceinline__ void cp_async16(uint32_t dst, const void* src) {
    asm volatile("cp.async.cg.shared.global [%0], [%1], 16;\n" :: "r"(dst), "l"(src));
}

// ---------------- elementwise tf32 rounding (rna, unbiased) ----------------
__global__ void round_tf32_kernel(const float4* __restrict__ in, float4* __restrict__ out, int n4) {
    int i = blockIdx.x * blockDim.x + threadIdx.x;
    if (i < n4) {
        float4 v = in[i];
        v.x = tf32r(v.x); v.y = tf32r(v.y); v.z = tf32r(v.z); v.w = tf32r(v.w);
        out[i] = v;
    }
}

// ---------------- RoPE table (fp64 for accuracy) ----------------
__global__ void rope_table_kernel() {
    int t = blockIdx.x;
    int i = threadIdx.x;                       // 0..63
    double inv = exp(-((double)(2*i) / 128.0) * 9.210340371976182736); // ln(10000)
    double ang = (double)t * inv;
    g_cos_t[t*64 + i] = (float)cos(ang);
    g_sin_t[t*64 + i] = (float)sin(ang);
}

// ---------------- tf32 tensor-core GEMM ----------------
// C[M,N] = A[M,K] @ B[K,N], row-major, A/B pre-rounded to tf32 values.
// 128x128 CTA tile, BK=16, 3-stage cp.async pipeline, 8 warps (4m x 2n),
// warp tile 32x64 via mma.sync.m16n8k8.tf32.
#define BM 128
#define BN 128
#define BK 16
#define ASTRIDE 20    // BK + 4  (pad: conflict-free A frag loads)
#define BSTRIDE 136   // BN + 8  (pad: conflict-free B frag loads)
#define STAGE_FLOATS (BM*ASTRIDE + BK*BSTRIDE)   // 2560 + 2176 = 4736
#define NSTAGES 3
#define GEMM_SMEM (NSTAGES*STAGE_FLOATS*4)       // 56832 B

__device__ __forceinline__ void gemm_issue_stage(
    const float* __restrict__ A, const float* __restrict__ B,
    float* sm_stage, int row0, int col0, int k0, int K, int N, int tid)
{
    float* As = sm_stage;
    float* Bs = sm_stage + BM*ASTRIDE;
    // A tile: 128 rows x 16 floats = 512 x 16B chunks
#pragma unroll
    for (int c = tid; c < 512; c += 256) {
        int r  = c >> 2;
        int kc = (c & 3) << 2;
        cp_async16(smem_u32(&As[r*ASTRIDE + kc]), A + (size_t)(row0 + r)*K + k0 + kc);
    }
    // B tile: 16 rows x 128 floats = 512 x 16B chunks
#pragma unroll
    for (int c = tid; c < 512; c += 256) {
        int r  = c >> 5;
        int nc = (c & 31) << 2;
        cp_async16(smem_u32(&Bs[r*BSTRIDE + nc]), B + (size_t)(k0 + r)*N + col0 + nc);
    }
    asm volatile("cp.async.commit_group;\n");
}

__global__ __launch_bounds__(256, 2)
void mma_gemm_tf32(const float* __restrict__ A, const float* __restrict__ B,
                   float* __restrict__ C, int M, int N, int K) {
    extern __shared__ float sm[];
    int tid  = threadIdx.x;
    int lane = tid & 31, wid = tid >> 5;
    int g = lane >> 2, tig = lane & 3;
    int wm = (wid >> 1) << 5;        // warp m origin: 0..96
    int wn = (wid & 1) << 6;         // warp n origin: 0 or 64
    int row0 = blockIdx.y * BM;
    int col0 = blockIdx.x * BN;

    float acc[2][8][4];
#pragma unroll
    for (int mt = 0; mt < 2; ++mt)
#pragma unroll
        for (int nt = 0; nt < 8; ++nt)
#pragma unroll
            for (int r = 0; r < 4; ++r) acc[mt][nt][r] = 0.f;

    int iters = K / BK;
    gemm_issue_stage(A, B, sm + 0*STAGE_FLOATS, row0, col0, 0,   K, N, tid);
    gemm_issue_stage(A, B, sm + 1*STAGE_FLOATS, row0, col0, BK,  K, N, tid);

    for (int it = 0; it < iters; ++it) {
        asm volatile("cp.async.wait_group %0;\n" :: "n"(1));
        __syncthreads();
        if (it + 2 < iters)
            gemm_issue_stage(A, B, sm + ((it+2) % NSTAGES)*STAGE_FLOATS,
                             row0, col0, (it+2)*BK, K, N, tid);

        const float* As = sm + (it % NSTAGES)*STAGE_FLOATS;
        const float* Bs = As + BM*ASTRIDE;
#pragma unroll
        for (int ks = 0; ks < 2; ++ks) {
            int kk = ks << 3;
            uint32_t a[2][4], b[8][2];
#pragma unroll
            for (int mt = 0; mt < 2; ++mt) {
                int r = wm + (mt << 4) + g;
                a[mt][0] = __float_as_uint(As[ r     *ASTRIDE + kk + tig    ]);
                a[mt][1] = __float_as_uint(As[(r + 8)*ASTRIDE + kk + tig    ]);
                a[mt][2] = __float_as_uint(As[ r     *ASTRIDE + kk + tig + 4]);
                a[mt][3] = __float_as_uint(As[(r + 8)*ASTRIDE + kk + tig + 4]);
            }
#pragma unroll
            for (int nt = 0; nt < 8; ++nt) {
                int ccol = wn + (nt << 3) + g;
                b[nt][0] = __float_as_uint(Bs[(kk + tig    )*BSTRIDE + ccol]);
                b[nt][1] = __float_as_uint(Bs[(kk + tig + 4)*BSTRIDE + ccol]);
            }
#pragma unroll
            for (int mt = 0; mt < 2; ++mt)
#pragma unroll
                for (int nt = 0; nt < 8; ++nt) {
                    asm volatile(
                        "mma.sync.aligned.m16n8k8.row.col.f32.tf32.tf32.f32 "
                        "{%0,%1,%2,%3}, {%4,%5,%6,%7}, {%8,%9}, {%0,%1,%2,%3};\n"
                        : "+f"(acc[mt][nt][0]), "+f"(acc[mt][nt][1]),
                          "+f"(acc[mt][nt][2]), "+f"(acc[mt][nt][3])
                        : "r"(a[mt][0]), "r"(a[mt][1]), "r"(a[mt][2]), "r"(a[mt][3]),
                          "r"(b[nt][0]), "r"(b[nt][1]));
                }
        }
        __syncthreads();
    }

    // epilogue: c0,c1 at (g, 2tig..2tig+1), c2,c3 at (g+8, same cols)
#pragma unroll
    for (int mt = 0; mt < 2; ++mt) {
#pragma unroll
        for (int nt = 0; nt < 8; ++nt) {
            int r    = row0 + wm + (mt << 4) + g;
            int ccol = col0 + wn + (nt << 3) + (tig << 1);
            *(float2*)(C + (size_t)r*N + ccol)       = make_float2(acc[mt][nt][0], acc[mt][nt][1]);
            *(float2*)(C + (size_t)(r + 8)*N + ccol) = make_float2(acc[mt][nt][2], acc[mt][nt][3]);
        }
    }
}

// ---------------- fused RoPE + transpose to (b, head, d, t) ----------------
__global__ void rope_transpose_kernel(const float* __restrict__ in, float* __restrict__ outT,
                                      int nheads, int rowWidth, float scale) {
    __shared__ float S[32][129];
    int t0 = blockIdx.x << 5;
    int h  = blockIdx.y;
    int b  = blockIdx.z;
    const float* base = in + ((size_t)b*T_ + t0)*rowWidth + h*HD_;
#pragma unroll
    for (int e = threadIdx.x; e < 32*32; e += 256) {
        int t  = e >> 5;
        int d4 = (e & 31) << 2;
        float4 v = *(const float4*)(base + (size_t)t*rowWidth + d4);
        S[t][d4+0] = v.x; S[t][d4+1] = v.y; S[t][d4+2] = v.z; S[t][d4+3] = v.w;
    }
    __syncthreads();
    float* obase = outT + ((size_t)(b*nheads + h)*HD_)*T_ + t0;
#pragma unroll
    for (int e = threadIdx.x; e < 32*128; e += 256) {
        int t  = e & 31;
        int d  = e >> 5;
        int dm = d & 63;
        float c = g_cos_t[(t0 + t)*64 + dm];
        float s = g_sin_t[(t0 + t)*64 + dm];
        float x1 = S[t][d];
        float x2 = (d < 64) ? S[t][d + 64] : S[t][d - 64];
        float val = (d < 64) ? (x1*c - x2*s) : (x1*c + x2*s);
        obase[(size_t)d*T_ + t] = val * scale;
    }
}

// ---------------- causal flash attention (fp32, online softmax) ----------------
#define FA_SMEM_FLOATS (128*68 + 128*68 + 64*132 + 64*68)
__global__ __launch_bounds__(256, 1)
void flash_kernel(const float* __restrict__ qT, const float* __restrict__ kT,
                  const float* __restrict__ v, float* __restrict__ out) {
    extern __shared__ float sm[];
    float* Qt = sm;                     // [128][68]  Qt[d][t]
    float* Kt = Qt + 128*68;            // [128][68]
    float* Vs = Kt + 128*68;            // [64][132]  Vs[t][d]
    float* Ps = Vs + 64*132;            // [64][68]

    int qt = gridDim.x - 1 - blockIdx.x;     // heavy tiles first
    int q0 = qt << 6;
    int bh = blockIdx.y;                     // b*16 + h
    int b  = bh >> 4, h = bh & 15;
    int kvh = h >> 2;
    int tid = threadIdx.x, tx = tid & 15, ty = tid >> 4;

    const float* qbase = qT + (size_t)bh * HD_ * T_;
    const float* kbase = kT + (size_t)(b*HKV_ + kvh) * HD_ * T_;
    const float* vbase = v  + (size_t)b * T_ * DKV_ + kvh*HD_;

#pragma unroll
    for (int e = tid; e < 2048; e += 256) {
        int d  = e >> 4;
        int t4 = (e & 15) << 2;
        *(float4*)&Qt[d*68 + t4] = *(const float4*)(qbase + (size_t)d*T_ + q0 + t4);
    }

    float o[4][8];
    float m[4], l[4];
#pragma unroll
    for (int i = 0; i < 4; ++i) {
        m[i] = -1e30f; l[i] = 0.f;
#pragma unroll
        for (int j = 0; j < 8; ++j) o[i][j] = 0.f;
    }

    for (int kt = 0; kt <= qt; ++kt) {
        int k0 = kt << 6;
#pragma unroll
        for (int e = tid; e < 2048; e += 256) {
            int d  = e >> 4;
            int t4 = (e & 15) << 2;
            *(float4*)&Kt[d*68 + t4] = *(const float4*)(kbase + (size_t)d*T_ + k0 + t4);
        }
#pragma unroll
        for (int e = tid; e < 2048; e += 256) {
            int t  = e >> 5;
            int d4 = (e & 31) << 2;
            *(float4*)&Vs[t*132 + d4] = *(const float4*)(vbase + (size_t)(k0 + t)*DKV_ + d4);
        }
        __syncthreads();

        float acc[4][4];
#pragma unroll
        for (int i = 0; i < 4; ++i)
#pragma unroll
            for (int j = 0; j < 4; ++j) acc[i][j] = 0.f;
#pragma unroll 8
        for (int d = 0; d < 128; ++d) {
            float4 qv = *(float4*)&Qt[d*68 + 4*ty];
            float4 kv = *(float4*)&Kt[d*68 + 4*tx];
            acc[0][0] += qv.x*kv.x; acc[0][1] += qv.x*kv.y; acc[0][2] += qv.x*kv.z; acc[0][3] += qv.x*kv.w;
            acc[1][0] += qv.y*kv.x; acc[1][1] += qv.y*kv.y; acc[1][2] += qv.y*kv.z; acc[1][3] += qv.y*kv.w;
            acc[2][0] += qv.z*kv.x; acc[2][1] += qv.z*kv.y; acc[2][2] += qv.z*kv.z; acc[2][3] += qv.z*kv.w;
            acc[3][0] += qv.w*kv.x; acc[3][1] += qv.w*kv.y; acc[3][2] += qv.w*kv.z; acc[3][3] += qv.w*kv.w;
        }

        if (kt == qt) {
#pragma unroll
            for (int i = 0; i < 4; ++i)
#pragma unroll
                for (int j = 0; j < 4; ++j)
                    if (4*tx + j > 4*ty + i) acc[i][j] = -1e30f;
        }

#pragma unroll
        for (int i = 0; i < 4; ++i) {
            float tm = fmaxf(fmaxf(acc[i][0], acc[i][1]), fmaxf(acc[i][2], acc[i][3]));
            tm = fmaxf(tm, __shfl_xor_sync(0xffffffffu, tm, 1));
            tm = fmaxf(tm, __shfl_xor_sync(0xffffffffu, tm, 2));
            tm = fmaxf(tm, __shfl_xor_sync(0xffffffffu, tm, 4));
            tm = fmaxf(tm, __shfl_xor_sync(0xffffffffu, tm, 8));
            float mn = fmaxf(m[i], tm);
            float corr = exp2f((m[i] - mn) * LOG2E);
            float rs = 0.f;
#pragma unroll
            for (int j = 0; j < 4; ++j) {
                float p = exp2f((acc[i][j] - mn) * LOG2E);
                acc[i][j] = p;
                rs += p;
            }
            rs += __shfl_xor_sync(0xffffffffu, rs, 1);
            rs += __shfl_xor_sync(0xffffffffu, rs, 2);
            rs += __shfl_xor_sync(0xffffffffu, rs, 4);
            rs += __shfl_xor_sync(0xffffffffu, rs, 8);
            l[i] = l[i] * corr + rs;
            m[i] = mn;
#pragma unroll
            for (int j = 0; j < 8; ++j) o[i][j] *= corr;
            *(float4*)&Ps[(4*ty + i)*68 + 4*tx] =
                make_float4(acc[i][0], acc[i][1], acc[i][2], acc[i][3]);
        }
        __syncthreads();

#pragma unroll 4
        for (int kk = 0; kk < 64; ++kk) {
            float4 v0 = *(float4*)&Vs[kk*132 + 8*tx];
            float4 v1 = *(float4*)&Vs[kk*132 + 8*tx + 4];
#pragma unroll
            for (int i = 0; i < 4; ++i) {
                float p = Ps[(4*ty + i)*68 + kk];
                o[i][0] += p*v0.x; o[i][1] += p*v0.y; o[i][2] += p*v0.z; o[i][3] += p*v0.w;
                o[i][4] += p*v1.x; o[i][5] += p*v1.y; o[i][6] += p*v1.z; o[i][7] += p*v1.w;
            }
        }
        __syncthreads();
    }

    // epilogue: divide by l, round to tf32 (unbiased) for the Wo GEMM input
#pragma unroll
    for (int i = 0; i < 4; ++i) {
        float inv = 1.f / l[i];
        float* orow = out + (size_t)(b*T_ + q0 + 4*ty + i)*D_ + h*HD_ + 8*tx;
        *(float4*)(orow)     = make_float4(tf32r(o[i][0]*inv), tf32r(o[i][1]*inv),
                                           tf32r(o[i][2]*inv), tf32r(o[i][3]*inv));
        *(float4*)(orow + 4) = make_float4(tf32r(o[i][4]*inv), tf32r(o[i][5]*inv),
                                           tf32r(o[i][6]*inv), tf32r(o[i][7]*inv));
    }
}

// ---------------- launch ----------------
extern "C" void kernel_launch(void* const* d_in, const int* in_sizes, int n_in,
                              void* d_out, int out_size) {
    const float* x  = (const float*)d_in[0];
    const float* Wq = (const float*)d_in[1];
    const float* Wk = (const float*)d_in[2];
    const float* Wv = (const float*)d_in[3];
    const float* Wo = (const float*)d_in[4];
    float* out = (float*)d_out;

    float *qtmp, *ktmp, *vbuf, *qT, *kT, *attn;
    float *xr, *wqr, *wkr, *wvr, *wor;
    cudaGetSymbolAddress((void**)&qtmp, g_q_tmp);
    cudaGetSymbolAddress((void**)&ktmp, g_k_tmp);
    cudaGetSymbolAddress((void**)&vbuf, g_v);
    cudaGetSymbolAddress((void**)&qT,   g_qT);
    cudaGetSymbolAddress((void**)&kT,   g_kT);
    cudaGetSymbolAddress((void**)&attn, g_attn);
    cudaGetSymbolAddress((void**)&xr,   g_xr);
    cudaGetSymbolAddress((void**)&wqr,  g_wqr);
    cudaGetSymbolAddress((void**)&wkr,  g_wkr);
    cudaGetSymbolAddress((void**)&wvr,  g_wvr);
    cudaGetSymbolAddress((void**)&wor,  g_wor);

    rope_table_kernel<<<T_, 64>>>();

    // unbiased tf32 rounding of all GEMM operands
    int n4x  = MROWS*D_/4;
    int n4qq = D_*D_/4;
    int n4kv = D_*DKV_/4;
    round_tf32_kernel<<<(n4x  + 255)/256, 256>>>((const float4*)x,  (float4*)xr,  n4x);
    round_tf32_kernel<<<(n4qq + 255)/256, 256>>>((const float4*)Wq, (float4*)wqr, n4qq);
    round_tf32_kernel<<<(n4kv + 255)/256, 256>>>((const float4*)Wk, (float4*)wkr, n4kv);
    round_tf32_kernel<<<(n4kv + 255)/256, 256>>>((const float4*)Wv, (float4*)wvr, n4kv);
    round_tf32_kernel<<<(n4qq + 255)/256, 256>>>((const float4*)Wo, (float4*)wor, n4qq);

    // projections on tensor cores
    cudaFuncSetAttribute(mma_gemm_tf32, cudaFuncAttributeMaxDynamicSharedMemorySize, GEMM_SMEM);
    mma_gemm_tf32<<<dim3(D_/BN,   MROWS/BM), 256, GEMM_SMEM>>>(xr, wqr, qtmp, MROWS, D_,   D_);
    mma_gemm_tf32<<<dim3(DKV_/BN, MROWS/BM), 256, GEMM_SMEM>>>(xr, wkr, ktmp, MROWS, DKV_, D_);
    mma_gemm_tf32<<<dim3(DKV_/BN, MROWS/BM), 256, GEMM_SMEM>>>(xr, wvr, vbuf, MROWS, DKV_, D_);

    // RoPE + transpose (scale 1/sqrt(hd) folded into Q)
    rope_transpose_kernel<<<dim3(T_/32, H_,   B_), 256>>>(qtmp, qT, H_,   D_,   0.08838834764831845f);
    rope_transpose_kernel<<<dim3(T_/32, HKV_, B_), 256>>>(ktmp, kT, HKV_, DKV_, 1.0f);

    // flash attention (fp32)
    static const int fa_smem = FA_SMEM_FLOATS * (int)sizeof(float);
    cudaFuncSetAttribute(flash_kernel, cudaFuncAttributeMaxDynamicSharedMemorySize, fa_smem);
    flash_kernel<<<dim3(T_/64, B_*H_), 256, fa_smem>>>(qT, kT, vbuf, attn);

    // output projection
    mma_gemm_tf32<<<dim3(D_/BN, MROWS/BM), 256, GEMM_SMEM>>>(attn, wor, out, MROWS, D_, D_);
}

// round 3
// speedup vs baseline: 3.3645x; 1.9502x over previous
#include <cuda_runtime.h>
#include <math.h>
#include <stdint.h>

// ---------------- problem constants ----------------
#define B_   2
#define T_   2048
#define D_   2048
#define H_   16
#define HKV_ 4
#define HD_  128
#define DKV_ (HKV_*HD_)    // 512
#define NQKV 3072          // fused q|k|v projection width
#define MROWS (B_*T_)      // 4096
// scale * log2(e) folded into Q (softmax uses exp2 directly)
#define QSCALE ((float)(1.4426950408889634 * 0.08838834764831845))

// ---------------- scratch (device globals) ----------------
__device__ float g_qkv [(size_t)MROWS * NQKV];       // fused projection out
__device__ float g_qr  [(size_t)B_*H_*T_*HD_];       // Q roped, (bh,t,d), tf32
__device__ float g_kr  [(size_t)B_*HKV_*T_*HD_];     // K roped, (bkh,t,d), tf32
__device__ float g_vT  [(size_t)B_*HKV_*HD_*T_];     // V^T, (bkh,d,t), tf32
__device__ float g_attn[(size_t)MROWS * D_];         // attention out (tf32)
__device__ float g_xr  [(size_t)MROWS * D_];         // x rounded
__device__ float g_wcat[(size_t)D_ * NQKV];          // [Wq|Wk|Wv] rounded
__device__ float g_wor [(size_t)D_ * D_];            // Wo rounded
__device__ float g_cos_t[T_*64];
__device__ float g_sin_t[T_*64];

// ---------------- helpers ----------------
__device__ __forceinline__ float tf32r(float x) {
    uint32_t u;
    asm("cvt.rna.tf32.f32 %0, %1;" : "=r"(u) : "f"(x));
    return __uint_as_float(u);
}
__device__ __forceinline__ uint32_t smem_u32(const void* p) {
    return (uint32_t)__cvta_generic_to_shared(p);
}
__device__ __forceinline__ void cp_async16(uint32_t dst, const void* src) {
    asm volatile("cp.async.cg.shared.global [%0], [%1], 16;\n" :: "r"(dst), "l"(src));
}
__device__ __forceinline__ void mma_tf32(float* c, const uint32_t* a, uint32_t b0, uint32_t b1) {
    asm volatile(
        "mma.sync.aligned.m16n8k8.row.col.f32.tf32.tf32.f32 "
        "{%0,%1,%2,%3}, {%4,%5,%6,%7}, {%8,%9}, {%0,%1,%2,%3};\n"
        : "+f"(c[0]), "+f"(c[1]), "+f"(c[2]), "+f"(c[3])
        : "r"(a[0]), "r"(a[1]), "r"(a[2]), "r"(a[3]), "r"(b0), "r"(b1));
}

// ---------------- RoPE table (fp64 precompute) ----------------
__global__ void rope_table_kernel() {
    int t = blockIdx.x;
    int i = threadIdx.x;                       // 0..63
    double inv = exp(-((double)(2*i) / 128.0) * 9.210340371976182736);
    double ang = (double)t * inv;
    g_cos_t[t*64 + i] = (float)cos(ang);
    g_sin_t[t*64 + i] = (float)sin(ang);
}

// ---------------- tf32 round + (optional) column-pack ----------------
__global__ void round_pack(const float4* __restrict__ in, float* __restrict__ out,
                           int n4, int ncols4, int outStride, int colOff) {
    int i = blockIdx.x * blockDim.x + threadIdx.x;
    if (i < n4) {
        float4 v = in[i];
        v.x = tf32r(v.x); v.y = tf32r(v.y); v.z = tf32r(v.z); v.w = tf32r(v.w);
        int k = i / ncols4;
        int n = (i - k*ncols4) << 2;
        *(float4*)(out + (size_t)k*outStride + colOff + n) = v;
    }
}

// ---------------- tf32 tensor-core GEMM (unchanged from round 2) ----------------
#define BM 128
#define BN 128
#define BK 16
#define ASTRIDE 20
#define BSTRIDE 136
#define STAGE_FLOATS (BM*ASTRIDE + BK*BSTRIDE)
#define NSTAGES 3
#define GEMM_SMEM (NSTAGES*STAGE_FLOATS*4)

__device__ __forceinline__ void gemm_issue_stage(
    const float* __restrict__ A, const float* __restrict__ B,
    float* sm_stage, int row0, int col0, int k0, int K, int N, int tid)
{
    float* As = sm_stage;
    float* Bs = sm_stage + BM*ASTRIDE;
#pragma unroll
    for (int c = tid; c < 512; c += 256) {
        int r  = c >> 2;
        int kc = (c & 3) << 2;
        cp_async16(smem_u32(&As[r*ASTRIDE + kc]), A + (size_t)(row0 + r)*K + k0 + kc);
    }
#pragma unroll
    for (int c = tid; c < 512; c += 256) {
        int r  = c >> 5;
        int nc = (c & 31) << 2;
        cp_async16(smem_u32(&Bs[r*BSTRIDE + nc]), B + (size_t)(k0 + r)*N + col0 + nc);
    }
    asm volatile("cp.async.commit_group;\n");
}

__global__ __launch_bounds__(256, 2)
void mma_gemm_tf32(const float* __restrict__ A, const float* __restrict__ B,
                   float* __restrict__ C, int M, int N, int K) {
    extern __shared__ float sm[];
    int tid  = threadIdx.x;
    int lane = tid & 31, wid = tid >> 5;
    int g = lane >> 2, tig = lane & 3;
    int wm = (wid >> 1) << 5;
    int wn = (wid & 1) << 6;
    int row0 = blockIdx.y * BM;
    int col0 = blockIdx.x * BN;

    float acc[2][8][4];
#pragma unroll
    for (int mt = 0; mt < 2; ++mt)
#pragma unroll
        for (int nt = 0; nt < 8; ++nt)
#pragma unroll
            for (int r = 0; r < 4; ++r) acc[mt][nt][r] = 0.f;

    int iters = K / BK;
    gemm_issue_stage(A, B, sm + 0*STAGE_FLOATS, row0, col0, 0,   K, N, tid);
    gemm_issue_stage(A, B, sm + 1*STAGE_FLOATS, row0, col0, BK,  K, N, tid);

    for (int it = 0; it < iters; ++it) {
        asm volatile("cp.async.wait_group %0;\n" :: "n"(1));
        __syncthreads();
        if (it + 2 < iters)
            gemm_issue_stage(A, B, sm + ((it+2) % NSTAGES)*STAGE_FLOATS,
                             row0, col0, (it+2)*BK, K, N, tid);

        const float* As = sm + (it % NSTAGES)*STAGE_FLOATS;
        const float* Bs = As + BM*ASTRIDE;
#pragma unroll
        for (int ks = 0; ks < 2; ++ks) {
            int kk = ks << 3;
            uint32_t a[2][4], b[8][2];
#pragma unroll
            for (int mt = 0; mt < 2; ++mt) {
                int r = wm + (mt << 4) + g;
                a[mt][0] = __float_as_uint(As[ r     *ASTRIDE + kk + tig    ]);
                a[mt][1] = __float_as_uint(As[(r + 8)*ASTRIDE + kk + tig    ]);
                a[mt][2] = __float_as_uint(As[ r     *ASTRIDE + kk + tig + 4]);
                a[mt][3] = __float_as_uint(As[(r + 8)*ASTRIDE + kk + tig + 4]);
            }
#pragma unroll
            for (int nt = 0; nt < 8; ++nt) {
                int ccol = wn + (nt << 3) + g;
                b[nt][0] = __float_as_uint(Bs[(kk + tig    )*BSTRIDE + ccol]);
                b[nt][1] = __float_as_uint(Bs[(kk + tig + 4)*BSTRIDE + ccol]);
            }
#pragma unroll
            for (int mt = 0; mt < 2; ++mt)
#pragma unroll
                for (int nt = 0; nt < 8; ++nt)
                    mma_tf32(acc[mt][nt], a[mt], b[nt][0], b[nt][1]);
        }
        __syncthreads();
    }

#pragma unroll
    for (int mt = 0; mt < 2; ++mt) {
#pragma unroll
        for (int nt = 0; nt < 8; ++nt) {
            int r    = row0 + wm + (mt << 4) + g;
            int ccol = col0 + wn + (nt << 3) + (tig << 1);
            *(float2*)(C + (size_t)r*N + ccol)       = make_float2(acc[mt][nt][0], acc[mt][nt][1]);
            *(float2*)(C + (size_t)(r + 8)*N + ccol) = make_float2(acc[mt][nt][2], acc[mt][nt][3]);
        }
    }
}

// ---------------- RoPE (elementwise) -> (bh, t, d), tf32-rounded ----------------
__global__ void rope_round(const float* __restrict__ in, float* __restrict__ out,
                           int nheads, int headOff, float scale) {
    int d = threadIdx.x;         // 0..127
    int t = blockIdx.x;
    int h = blockIdx.y;
    int b = blockIdx.z;
    const float* row = in + ((size_t)(b*T_ + t))*NQKV + headOff + h*HD_;
    float x1 = row[d];
    float x2 = row[(d < 64) ? d + 64 : d - 64];
    float c = g_cos_t[t*64 + (d & 63)];
    float s = g_sin_t[t*64 + (d & 63)];
    float val = (d < 64) ? (x1*c - x2*s) : (x1*c + x2*s);
    out[(((size_t)(b*nheads + h))*T_ + t)*HD_ + d] = tf32r(val * scale);
}

// ---------------- V transpose -> (bkh, d, t), tf32-rounded ----------------
__global__ void vtrans_round(const float* __restrict__ in, float* __restrict__ out) {
    __shared__ float S[32][33];
    int t0 = blockIdx.x << 5;
    int kh = blockIdx.y >> 2;
    int d0 = (blockIdx.y & 3) << 5;
    int b  = blockIdx.z;
    for (int e = threadIdx.x; e < 1024; e += 256) {
        int t = e >> 5, d = e & 31;
        S[t][d] = in[((size_t)(b*T_ + t0 + t))*NQKV + 2560 + kh*HD_ + d0 + d];
    }
    __syncthreads();
    float* obase = out + ((size_t)(b*HKV_ + kh)*HD_)*T_;
    for (int e = threadIdx.x; e < 1024; e += 256) {
        int d = e >> 5, t = e & 31;
        obase[(size_t)(d0 + d)*T_ + t0 + t] = tf32r(S[t][d]);
    }
}

// ---------------- tensor-core causal flash attention ----------------
// Q tile 128 x (hd=128), K/V tile 64. 256 threads / 8 warps.
// S phase: warp w owns m16 strip (rows 16w..16w+15), full n=64; Q frags in regs.
// PV phase: warps 4m x 2n (m32 x n64 tiles).
#define FKS0 0
#define FKS1 8448
#define FVT0 16896
#define FVT1 25600
#define FPS  34304
#define FCS  43008
#define FSM_FLOATS 43168
#define FSM_BYTES  (FSM_FLOATS*4)

__device__ __forceinline__ void fa_issue(const float* __restrict__ kbase,
                                         const float* __restrict__ vbase,
                                         float* sm, int buf, int k0, int tid) {
    float* Ks = sm + (buf ? FKS1 : FKS0);
    float* Vt = sm + (buf ? FVT1 : FVT0);
#pragma unroll
    for (int i = 0; i < 8; ++i) {               // K tile: 64 rows x 128 d
        int c = tid + i*256;
        int row = c >> 5, d4 = (c & 31) << 2;
        cp_async16(smem_u32(&Ks[row*132 + d4]), kbase + (size_t)(k0 + row)*HD_ + d4);
    }
#pragma unroll
    for (int i = 0; i < 8; ++i) {               // V^T tile: 128 d x 64 t
        int c = tid + i*256;
        int d = c >> 4, t4 = (c & 15) << 2;
        cp_async16(smem_u32(&Vt[d*68 + t4]), vbase + (size_t)d*T_ + k0 + t4);
    }
    asm volatile("cp.async.commit_group;\n");
}

__global__ __launch_bounds__(256, 1)
void flash_tc(const float* __restrict__ qr, const float* __restrict__ kr,
              const float* __restrict__ vT, float* __restrict__ attn) {
    extern __shared__ float sm[];
    float* Ps = sm + FPS;
    float* cs = sm + FCS;

    int tid = threadIdx.x, lane = tid & 31, wid = tid >> 5;
    int g = lane >> 2, tig = lane & 3;
    int qi = gridDim.x - 1 - blockIdx.x;        // heavy tiles first
    int q0 = qi << 7;
    int bh = blockIdx.y;
    int b = bh >> 4, h = bh & 15, kvh = h >> 2;
    int nkt = 2*qi + 2;

    const float* qbase = qr + ((size_t)bh * T_) * HD_;
    const float* kbase = kr + ((size_t)(b*HKV_ + kvh) * T_) * HD_;
    const float* vbase = vT + ((size_t)(b*HKV_ + kvh) * HD_) * T_;

    fa_issue(kbase, vbase, sm, 0, 0, tid);      // prefetch kt=0

    // preload Q fragments (16 ksteps x 4 regs), overlaps with cp.async
    int wm = wid << 4;
    uint32_t qf[16][4];
    {
        const float* r0p = qbase + (size_t)(q0 + wm + g)*HD_;
        const float* r1p = qbase + (size_t)(q0 + wm + g + 8)*HD_;
#pragma unroll
        for (int ks = 0; ks < 16; ++ks) {
            qf[ks][0] = __float_as_uint(__ldg(r0p + 8*ks + tig));
            qf[ks][1] = __float_as_uint(__ldg(r1p + 8*ks + tig));
            qf[ks][2] = __float_as_uint(__ldg(r0p + 8*ks + tig + 4));
            qf[ks][3] = __float_as_uint(__ldg(r1p + 8*ks + tig + 4));
        }
    }

    int pm = wid >> 1, pn = wid & 1;            // PV warp layout
    float o[2][8][4];
#pragma unroll
    for (int mt = 0; mt < 2; ++mt)
#pragma unroll
        for (int nt = 0; nt < 8; ++nt)
#pragma unroll
            for (int r = 0; r < 4; ++r) o[mt][nt][r] = 0.f;
    float m0 = -1e30f, m1 = -1e30f, l0 = 0.f, l1 = 0.f;

    for (int kt = 0; kt < nkt; ++kt) {
        if (kt + 1 < nkt) {
            fa_issue(kbase, vbase, sm, (kt+1) & 1, (kt+1) << 6, tid);
            asm volatile("cp.async.wait_group %0;\n" :: "n"(1));
        } else {
            asm volatile("cp.async.wait_group %0;\n" :: "n"(0));
        }
        __syncthreads();

        const float* Ks = sm + ((kt & 1) ? FKS1 : FKS0);
        const float* Vt = sm + ((kt & 1) ? FVT1 : FVT0);

        // ---- S = Q K^T ----
        float sacc[8][4];
#pragma unroll
        for (int nt = 0; nt < 8; ++nt)
#pragma unroll
            for (int r = 0; r < 4; ++r) sacc[nt][r] = 0.f;
#pragma unroll
        for (int ks = 0; ks < 16; ++ks) {
            int kk = 8*ks + tig;
#pragma unroll
            for (int nt = 0; nt < 8; ++nt) {
                uint32_t b0 = __float_as_uint(Ks[(8*nt + g)*132 + kk]);
                uint32_t b1 = __float_as_uint(Ks[(8*nt + g)*132 + kk + 4]);
                mma_tf32(sacc[nt], qf[ks], b0, b1);
            }
        }

        // ---- causal mask (only on the two diagonal k-tiles) ----
        if (kt >= nkt - 2) {
            int k0 = kt << 6;
            int r0 = q0 + wm + g, r1 = r0 + 8;
#pragma unroll
            for (int nt = 0; nt < 8; ++nt) {
                int c0 = k0 + 8*nt + 2*tig, c1 = c0 + 1;
                if (c0 > r0) sacc[nt][0] = -1e30f;
                if (c1 > r0) sacc[nt][1] = -1e30f;
                if (c0 > r1) sacc[nt][2] = -1e30f;
                if (c1 > r1) sacc[nt][3] = -1e30f;
            }
        }

        // ---- online softmax (scores already in log2 units) ----
        float rm0 = -1e30f, rm1 = -1e30f;
#pragma unroll
        for (int nt = 0; nt < 8; ++nt) {
            rm0 = fmaxf(rm0, fmaxf(sacc[nt][0], sacc[nt][1]));
            rm1 = fmaxf(rm1, fmaxf(sacc[nt][2], sacc[nt][3]));
        }
        rm0 = fmaxf(rm0, __shfl_xor_sync(0xffffffffu, rm0, 1));
        rm0 = fmaxf(rm0, __shfl_xor_sync(0xffffffffu, rm0, 2));
        rm1 = fmaxf(rm1, __shfl_xor_sync(0xffffffffu, rm1, 1));
        rm1 = fmaxf(rm1, __shfl_xor_sync(0xffffffffu, rm1, 2));
        float mn0 = fmaxf(m0, rm0), mn1 = fmaxf(m1, rm1);
        float corr0 = exp2f(m0 - mn0), corr1 = exp2f(m1 - mn1);
        m0 = mn0; m1 = mn1;

        float rs0 = 0.f, rs1 = 0.f;
#pragma unroll
        for (int nt = 0; nt < 8; ++nt) {
            float p00 = exp2f(sacc[nt][0] - mn0);
            float p01 = exp2f(sacc[nt][1] - mn0);
            float p10 = exp2f(sacc[nt][2] - mn1);
            float p11 = exp2f(sacc[nt][3] - mn1);
            rs0 += p00 + p01;
            rs1 += p10 + p11;
            *(float2*)&Ps[(wm + g)*68 + 8*nt + 2*tig]     = make_float2(tf32r(p00), tf32r(p01));
            *(float2*)&Ps[(wm + g + 8)*68 + 8*nt + 2*tig] = make_float2(tf32r(p10), tf32r(p11));
        }
        rs0 += __shfl_xor_sync(0xffffffffu, rs0, 1);
        rs0 += __shfl_xor_sync(0xffffffffu, rs0, 2);
        rs1 += __shfl_xor_sync(0xffffffffu, rs1, 1);
        rs1 += __shfl_xor_sync(0xffffffffu, rs1, 2);
        l0 = l0*corr0 + rs0;
        l1 = l1*corr1 + rs1;
        if (tig == 0) { cs[wm + g] = corr0; cs[wm + g + 8] = corr1; }
        __syncthreads();

        // ---- rescale O then O += P V  (warps as 4m x 2n) ----
#pragma unroll
        for (int mt = 0; mt < 2; ++mt) {
            int rb = 32*pm + 16*mt;
            float c0 = cs[rb + g], c1 = cs[rb + g + 8];
#pragma unroll
            for (int nt = 0; nt < 8; ++nt) {
                o[mt][nt][0] *= c0; o[mt][nt][1] *= c0;
                o[mt][nt][2] *= c1; o[mt][nt][3] *= c1;
            }
        }
#pragma unroll
        for (int ks = 0; ks < 8; ++ks) {
            int kk = 8*ks + tig;
            uint32_t a[2][4];
#pragma unroll
            for (int mt = 0; mt < 2; ++mt) {
                int rb = 32*pm + 16*mt;
                a[mt][0] = __float_as_uint(Ps[(rb + g)*68 + kk]);
                a[mt][1] = __float_as_uint(Ps[(rb + g + 8)*68 + kk]);
                a[mt][2] = __float_as_uint(Ps[(rb + g)*68 + kk + 4]);
                a[mt][3] = __float_as_uint(Ps[(rb + g + 8)*68 + kk + 4]);
            }
#pragma unroll
            for (int nt = 0; nt < 8; ++nt) {
                uint32_t b0 = __float_as_uint(Vt[(64*pn + 8*nt + g)*68 + kk]);
                uint32_t b1 = __float_as_uint(Vt[(64*pn + 8*nt + g)*68 + kk + 4]);
                mma_tf32(o[0][nt], a[0], b0, b1);
                mma_tf32(o[1][nt], a[1], b0, b1);
            }
        }
        __syncthreads();
    }

    // publish l (S-phase row ownership) then divide + store (PV-phase ownership)
    float* ls = cs;
    if (tig == 0) { ls[wm + g] = l0; ls[wm + g + 8] = l1; }
    __syncthreads();

#pragma unroll
    for (int mt = 0; mt < 2; ++mt) {
        int rb = 32*pm + 16*mt;
        float inv0 = 1.f / ls[rb + g];
        float inv1 = 1.f / ls[rb + g + 8];
        int gr0 = q0 + rb + g, gr1 = gr0 + 8;
#pragma unroll
        for (int nt = 0; nt < 8; ++nt) {
            int dcol = 64*pn + 8*nt + 2*tig;
            *(float2*)(attn + ((size_t)(b*T_ + gr0))*D_ + h*HD_ + dcol) =
                make_float2(tf32r(o[mt][nt][0]*inv0), tf32r(o[mt][nt][1]*inv0));
            *(float2*)(attn + ((size_t)(b*T_ + gr1))*D_ + h*HD_ + dcol) =
                make_float2(tf32r(o[mt][nt][2]*inv1), tf32r(o[mt][nt][3]*inv1));
        }
    }
}

// ---------------- launch ----------------
extern "C" void kernel_launch(void* const* d_in, const int* in_sizes, int n_in,
                              void* d_out, int out_size) {
    const float* x  = (const float*)d_in[0];
    const float* Wq = (const float*)d_in[1];
    const float* Wk = (const float*)d_in[2];
    const float* Wv = (const float*)d_in[3];
    const float* Wo = (const float*)d_in[4];
    float* out = (float*)d_out;

    float *qkv, *qr, *kr, *vT, *attn, *xr, *wcat, *wor;
    cudaGetSymbolAddress((void**)&qkv,  g_qkv);
    cudaGetSymbolAddress((void**)&qr,   g_qr);
    cudaGetSymbolAddress((void**)&kr,   g_kr);
    cudaGetSymbolAddress((void**)&vT,   g_vT);
    cudaGetSymbolAddress((void**)&attn, g_attn);
    cudaGetSymbolAddress((void**)&xr,   g_xr);
    cudaGetSymbolAddress((void**)&wcat, g_wcat);
    cudaGetSymbolAddress((void**)&wor,  g_wor);

    rope_table_kernel<<<T_, 64>>>();

    // tf32 rounding (+ weight concat into wcat)
    int n4x  = MROWS*D_/4;
    int n4qq = D_*D_/4;
    int n4kv = D_*DKV_/4;
    round_pack<<<(n4x  + 255)/256, 256>>>((const float4*)x,  xr,   n4x,  D_/4,   D_,   0);
    round_pack<<<(n4qq + 255)/256, 256>>>((const float4*)Wq, wcat, n4qq, D_/4,   NQKV, 0);
    round_pack<<<(n4kv + 255)/256, 256>>>((const float4*)Wk, wcat, n4kv, DKV_/4, NQKV, 2048);
    round_pack<<<(n4kv + 255)/256, 256>>>((const float4*)Wv, wcat, n4kv, DKV_/4, NQKV, 2560);
    round_pack<<<(n4qq + 255)/256, 256>>>((const float4*)Wo, wor,  n4qq, D_/4,   D_,   0);

    // fused QKV projection on tensor cores
    cudaFuncSetAttribute(mma_gemm_tf32, cudaFuncAttributeMaxDynamicSharedMemorySize, GEMM_SMEM);
    mma_gemm_tf32<<<dim3(NQKV/BN, MROWS/BM), 256, GEMM_SMEM>>>(xr, wcat, qkv, MROWS, NQKV, D_);

    // RoPE (+scale*log2e fold for Q) and V transpose, all tf32-rounded
    rope_round<<<dim3(T_, H_,   B_), 128>>>(qkv, qr, H_,   0,    QSCALE);
    rope_round<<<dim3(T_, HKV_, B_), 128>>>(qkv, kr, HKV_, 2048, 1.0f);
    vtrans_round<<<dim3(T_/32, 16, B_), 256>>>(qkv, vT);

    // tensor-core flash attention
    cudaFuncSetAttribute(flash_tc, cudaFuncAttributeMaxDynamicSharedMemorySize, FSM_BYTES);
    flash_tc<<<dim3(T_/128, B_*H_), 256, FSM_BYTES>>>(qr, kr, vT, attn);

    // output projection
    mma_gemm_tf32<<<dim3(D_/BN, MROWS/BM), 256, GEMM_SMEM>>>(attn, wor, out, MROWS, D_, D_);
}

// round 5
// speedup vs baseline: 5.4819x; 1.6293x over previous
#include <cuda_runtime.h>
#include <cuda_fp16.h>
#include <math.h>
#include <stdint.h>

// ---------------- problem constants ----------------
#define B_   2
#define T_   2048
#define D_   2048
#define H_   16
#define HKV_ 4
#define HD_  128
#define DKV_ (HKV_*HD_)    // 512
#define NQKV 3072          // fused q|k|v projection width
#define MROWS (B_*T_)      // 4096
#define QSCALE ((float)(1.4426950408889634 * 0.08838834764831845))

// ---------------- scratch (device globals) ----------------
__device__ float  g_qkv [(size_t)MROWS * NQKV];                 // fused projection out (f32)
__device__ __align__(16) __half g_xh   [(size_t)MROWS * D_];    // x in fp16
__device__ __align__(16) __half g_wcatT[(size_t)NQKV * D_];     // [Wq|Wk|Wv]^T fp16: [n][k]
__device__ __align__(16) __half g_worT [(size_t)D_ * D_];       // Wo^T fp16: [n][k]
__device__ __align__(16) __half g_qr   [(size_t)B_*H_*T_*HD_];  // Q roped, (bh,t,d)
__device__ __align__(16) __half g_kr   [(size_t)B_*HKV_*T_*HD_];// K roped
__device__ __align__(16) __half g_vT   [(size_t)B_*HKV_*HD_*T_];// V^T, (bkh,d,t)
__device__ __align__(16) __half g_attn [(size_t)MROWS * D_];    // attention out fp16
__device__ float g_cos_t[T_*64];
__device__ float g_sin_t[T_*64];

// ---------------- helpers ----------------
__device__ __forceinline__ uint32_t smem_u32(const void* p) {
    return (uint32_t)__cvta_generic_to_shared(p);
}
__device__ __forceinline__ void cp_async16(uint32_t dst, const void* src) {
    asm volatile("cp.async.cg.shared.global [%0], [%1], 16;\n" :: "r"(dst), "l"(src));
}
__device__ __forceinline__ void mma_f16(float* c, const uint32_t* a, uint32_t b0, uint32_t b1) {
    asm volatile(
        "mma.sync.aligned.m16n8k16.row.col.f32.f16.f16.f32 "
        "{%0,%1,%2,%3}, {%4,%5,%6,%7}, {%8,%9}, {%0,%1,%2,%3};\n"
        : "+f"(c[0]), "+f"(c[1]), "+f"(c[2]), "+f"(c[3])
        : "r"(a[0]), "r"(a[1]), "r"(a[2]), "r"(a[3]), "r"(b0), "r"(b1));
}
__device__ __forceinline__ uint32_t h2u(float a, float b) {
    __half2 h = __floats2half2_rn(a, b);
    return *(uint32_t*)&h;
}

// ---------------- RoPE table (fp64 precompute) ----------------
__global__ void rope_table_kernel() {
    int t = blockIdx.x;
    int i = threadIdx.x;                       // 0..63
    double inv = exp(-((double)(2*i) / 128.0) * 9.210340371976182736);
    double ang = (double)t * inv;
    g_cos_t[t*64 + i] = (float)cos(ang);
    g_sin_t[t*64 + i] = (float)sin(ang);
}

// ---------------- f32 -> fp16 conversion ----------------
__global__ void conv_half(const float4* __restrict__ in, __half2* __restrict__ out, int n4) {
    int i = blockIdx.x * blockDim.x + threadIdx.x;
    if (i < n4) {
        float4 v = in[i];
        out[2*i]     = __floats2half2_rn(v.x, v.y);
        out[2*i + 1] = __floats2half2_rn(v.z, v.w);
    }
}

// ---------------- transpose + fp16:  out[n][k] = h(in[k][n]) ----------------
__global__ void trans_half(const float* __restrict__ in, __half* __restrict__ out,
                           int cols, int ostride) {
    __shared__ float S[32][33];
    int k0 = blockIdx.y << 5;
    int n0 = blockIdx.x << 5;
    for (int e = threadIdx.x; e < 1024; e += 256) {
        int r = e >> 5, c = e & 31;
        S[r][c] = in[(size_t)(k0 + r)*cols + n0 + c];
    }
    __syncthreads();
    for (int e = threadIdx.x; e < 1024; e += 256) {
        int r = e >> 5, c = e & 31;
        out[(size_t)(n0 + r)*ostride + k0 + c] = __float2half_rn(S[c][r]);
    }
}

// ---------------- fp16 tensor-core GEMM: C[M,N] = A[M,K] @ Bt[N,K]^T ----------------
// 128x128 CTA tile, BK=32 halfs, 3-stage cp.async, 8 warps (4m x 2n),
// warp tile 32x64 via mma.m16n8k16.f16 (f32 accum).
#define BKH 32
#define ASTR 40                                  // padded row stride (halfs)
#define STG_HALFS (2*128*ASTR)                   // A tile + B tile per stage
#define GM_SMEM   (3*STG_HALFS*2)                // bytes

__device__ __forceinline__ void gemm_issue(const __half* __restrict__ Ag,
                                           const __half* __restrict__ Bg,
                                           uint32_t sbase, int K, int tid) {
    uint32_t sB = sbase + 128*ASTR*2;
#pragma unroll
    for (int i = 0; i < 2; ++i) {                // A: 128 rows x 4 chunks
        int c = tid + (i << 8);
        int r = c >> 2, cb = (c & 3) << 3;
        cp_async16(sbase + (r*ASTR + cb)*2, Ag + (size_t)r*K + cb);
    }
#pragma unroll
    for (int i = 0; i < 2; ++i) {                // B: 128 rows x 4 chunks
        int c = tid + (i << 8);
        int r = c >> 2, cb = (c & 3) << 3;
        cp_async16(sB + (r*ASTR + cb)*2, Bg + (size_t)r*K + cb);
    }
    asm volatile("cp.async.commit_group;\n");
}

__global__ __launch_bounds__(256, 2)
void gemm_f16(const __half* __restrict__ A, const __half* __restrict__ Bt,
              float* __restrict__ C, int M, int N, int K, int ldc) {
    extern __shared__ __half smh[];
    uint32_t sbase = smem_u32(smh);
    int tid  = threadIdx.x;
    int lane = tid & 31, wid = tid >> 5;
    int g = lane >> 2, tig = lane & 3;
    int wm = (wid >> 1) << 5;
    int wn = (wid & 1) << 6;
    int row0 = blockIdx.y << 7;
    int col0 = blockIdx.x << 7;

    const __half* Abase = A  + (size_t)row0 * K;
    const __half* Bbase = Bt + (size_t)col0 * K;

    float acc[2][8][4];
#pragma unroll
    for (int mt = 0; mt < 2; ++mt)
#pragma unroll
        for (int nt = 0; nt < 8; ++nt)
#pragma unroll
            for (int r = 0; r < 4; ++r) acc[mt][nt][r] = 0.f;

    int iters = K / BKH;
    gemm_issue(Abase,       Bbase,       sbase,               K, tid);
    gemm_issue(Abase + BKH, Bbase + BKH, sbase + STG_HALFS*2, K, tid);

    for (int it = 0; it < iters; ++it) {
        if (it + 2 < iters) {
            asm volatile("cp.async.wait_group %0;\n" :: "n"(1));
        } else {
            asm volatile("cp.async.wait_group %0;\n" :: "n"(0));
        }
        __syncthreads();
        if (it + 2 < iters)
            gemm_issue(Abase + (it+2)*BKH, Bbase + (it+2)*BKH,
                       sbase + ((it+2) % 3)*STG_HALFS*2, K, tid);

        const __half* As = smh + (it % 3)*STG_HALFS;
        const __half* Bs = As + 128*ASTR;
#pragma unroll
        for (int ks = 0; ks < 2; ++ks) {
            int kk = (ks << 4) + (tig << 1);
            uint32_t a[2][4], b[8][2];
#pragma unroll
            for (int mt = 0; mt < 2; ++mt) {
                int r = wm + (mt << 4) + g;
                a[mt][0] = *(const uint32_t*)&As[ r     *ASTR + kk];
                a[mt][1] = *(const uint32_t*)&As[(r + 8)*ASTR + kk];
                a[mt][2] = *(const uint32_t*)&As[ r     *ASTR + kk + 8];
                a[mt][3] = *(const uint32_t*)&As[(r + 8)*ASTR + kk + 8];
            }
#pragma unroll
            for (int nt = 0; nt < 8; ++nt) {
                int n = wn + (nt << 3) + g;
                b[nt][0] = *(const uint32_t*)&Bs[n*ASTR + kk];
                b[nt][1] = *(const uint32_t*)&Bs[n*ASTR + kk + 8];
            }
#pragma unroll
            for (int mt = 0; mt < 2; ++mt)
#pragma unroll
                for (int nt = 0; nt < 8; ++nt)
                    mma_f16(acc[mt][nt], a[mt], b[nt][0], b[nt][1]);
        }
        __syncthreads();
    }

#pragma unroll
    for (int mt = 0; mt < 2; ++mt) {
#pragma unroll
        for (int nt = 0; nt < 8; ++nt) {
            int r    = row0 + wm + (mt << 4) + g;
            int ccol = col0 + wn + (nt << 3) + (tig << 1);
            *(float2*)(C + (size_t)r*ldc + ccol)       = make_float2(acc[mt][nt][0], acc[mt][nt][1]);
            *(float2*)(C + (size_t)(r + 8)*ldc + ccol) = make_float2(acc[mt][nt][2], acc[mt][nt][3]);
        }
    }
}

// ---------------- RoPE (elementwise) -> (bh, t, d) fp16 ----------------
__global__ void rope_round_h(const float* __restrict__ in, __half* __restrict__ out,
                             int nheads, int headOff, float scale) {
    int d = threadIdx.x;         // 0..127
    int t = blockIdx.x;
    int h = blockIdx.y;
    int b = blockIdx.z;
    const float* row = in + ((size_t)(b*T_ + t))*NQKV + headOff + h*HD_;
    float x1 = row[d];
    float x2 = row[(d < 64) ? d + 64 : d - 64];
    float c = g_cos_t[t*64 + (d & 63)];
    float s = g_sin_t[t*64 + (d & 63)];
    float val = (d < 64) ? (x1*c - x2*s) : (x1*c + x2*s);
    out[(((size_t)(b*nheads + h))*T_ + t)*HD_ + d] = __float2half_rn(val * scale);
}

// ---------------- V transpose -> (bkh, d, t) fp16 ----------------
__global__ void vtrans_h(const float* __restrict__ in, __half* __restrict__ out) {
    __shared__ float S[32][33];
    int t0 = blockIdx.x << 5;
    int kh = blockIdx.y >> 2;
    int d0 = (blockIdx.y & 3) << 5;
    int b  = blockIdx.z;
    for (int e = threadIdx.x; e < 1024; e += 256) {
        int t = e >> 5, d = e & 31;
        S[t][d] = in[((size_t)(b*T_ + t0 + t))*NQKV + 2560 + kh*HD_ + d0 + d];
    }
    __syncthreads();
    __half* obase = out + ((size_t)(b*HKV_ + kh)*HD_)*T_;
    for (int e = threadIdx.x; e < 1024; e += 256) {
        int d = e >> 5, t = e & 31;
        obase[(size_t)(d0 + d)*T_ + t0 + t] = __float2half_rn(S[t][d]);
    }
}

// ---------------- fp16 tensor-core causal flash attention ----------------
// Q tile 128, K/V tile 64, hd=128. 256 threads / 8 warps.
// S phase: warp w owns rows 16w..16w+15. PV: warps 4m x 2n.
#define FK_STR 136
#define FV_STR 72
#define FP_STR 72
#define FKS0 0
#define FKS1 (64*FK_STR)                  // 8704
#define FVT0 (2*64*FK_STR)                // 17408
#define FVT1 (FVT0 + 128*FV_STR)          // 26624
#define FPS  (FVT0 + 2*128*FV_STR)        // 35840
#define FSM_HALFS (FPS + 128*FP_STR)      // 45056
#define FSM_BYTES (FSM_HALFS*2 + 512)     // + cs (128 floats)

__device__ __forceinline__ void fa_issue(const __half* __restrict__ kbase,
                                         const __half* __restrict__ vbase,
                                         uint32_t sbase, int buf, int k0, int tid) {
    uint32_t ks = sbase + (buf ? FKS1 : FKS0)*2;
    uint32_t vt = sbase + (buf ? FVT1 : FVT0)*2;
#pragma unroll
    for (int i = 0; i < 4; ++i) {                 // K: 64 rows x 16 chunks
        int c = tid + (i << 8);
        int row = c >> 4, cb = (c & 15) << 3;
        cp_async16(ks + (row*FK_STR + cb)*2, kbase + (size_t)(k0 + row)*HD_ + cb);
    }
#pragma unroll
    for (int i = 0; i < 4; ++i) {                 // V^T: 128 d-rows x 8 chunks
        int c = tid + (i << 8);
        int d = c >> 3, cb = (c & 7) << 3;
        cp_async16(vt + (d*FV_STR + cb)*2, vbase + (size_t)d*T_ + k0 + cb);
    }
    asm volatile("cp.async.commit_group;\n");
}

__global__ __launch_bounds__(256, 1)
void flash_f16(const __half* __restrict__ qr, const __half* __restrict__ kr,
               const __half* __restrict__ vT, __half* __restrict__ attn) {
    extern __shared__ __half smh[];
    uint32_t sbase = smem_u32(smh);
    __half* Ps = smh + FPS;
    float*  cs = (float*)(smh + FSM_HALFS);

    int tid = threadIdx.x, lane = tid & 31, wid = tid >> 5;
    int g = lane >> 2, tig = lane & 3;
    int qi = gridDim.x - 1 - blockIdx.x;          // heavy tiles first
    int q0 = qi << 7;
    int bh = blockIdx.y;
    int b = bh >> 4, h = bh & 15, kvh = h >> 2;
    int nkt = 2*qi + 2;

    const __half* qbase = qr + ((size_t)bh * T_) * HD_;
    const __half* kbase = kr + ((size_t)(b*HKV_ + kvh) * T_) * HD_;
    const __half* vbase = vT + ((size_t)(b*HKV_ + kvh) * HD_) * T_;

    fa_issue(kbase, vbase, sbase, 0, 0, tid);

    // preload Q fragments: 8 ksteps x 4 half2 regs
    int wm = wid << 4;
    uint32_t qf[8][4];
    {
        const __half* r0p = qbase + (size_t)(q0 + wm + g)*HD_;
        const __half* r1p = qbase + (size_t)(q0 + wm + g + 8)*HD_;
#pragma unroll
        for (int ks = 0; ks < 8; ++ks) {
            int kk = (ks << 4) + (tig << 1);
            qf[ks][0] = __ldg((const uint32_t*)(r0p + kk));
            qf[ks][1] = __ldg((const uint32_t*)(r1p + kk));
            qf[ks][2] = __ldg((const uint32_t*)(r0p + kk + 8));
            qf[ks][3] = __ldg((const uint32_t*)(r1p + kk + 8));
        }
    }

    int pm = wid >> 1, pn = wid & 1;              // PV warp layout
    float o[2][8][4];
#pragma unroll
    for (int mt = 0; mt < 2; ++mt)
#pragma unroll
        for (int nt = 0; nt < 8; ++nt)
#pragma unroll
            for (int r = 0; r < 4; ++r) o[mt][nt][r] = 0.f;
    float m0 = -1e30f, m1 = -1e30f, l0 = 0.f, l1 = 0.f;

    for (int kt = 0; kt < nkt; ++kt) {
        if (kt + 1 < nkt) {
            fa_issue(kbase, vbase, sbase, (kt+1) & 1, (kt+1) << 6, tid);
            asm volatile("cp.async.wait_group %0;\n" :: "n"(1));
        } else {
            asm volatile("cp.async.wait_group %0;\n" :: "n"(0));
        }
        __syncthreads();

        const __half* Ks = smh + ((kt & 1) ? FKS1 : FKS0);
        const __half* Vt = smh + ((kt & 1) ? FVT1 : FVT0);

        // ---- S = Q K^T ----
        float sacc[8][4];
#pragma unroll
        for (int nt = 0; nt < 8; ++nt)
#pragma unroll
            for (int r = 0; r < 4; ++r) sacc[nt][r] = 0.f;
#pragma unroll
        for (int ks = 0; ks < 8; ++ks) {
            int kk = (ks << 4) + (tig << 1);
#pragma unroll
            for (int nt = 0; nt < 8; ++nt) {
                uint32_t b0 = *(const uint32_t*)&Ks[(8*nt + g)*FK_STR + kk];
                uint32_t b1 = *(const uint32_t*)&Ks[(8*nt + g)*FK_STR + kk + 8];
                mma_f16(sacc[nt], qf[ks], b0, b1);
            }
        }

        // ---- causal mask on the two diagonal k-tiles ----
        if (kt >= nkt - 2) {
            int k0 = kt << 6;
            int r0 = q0 + wm + g, r1 = r0 + 8;
#pragma unroll
            for (int nt = 0; nt < 8; ++nt) {
                int c0 = k0 + 8*nt + 2*tig, c1 = c0 + 1;
                if (c0 > r0) sacc[nt][0] = -1e30f;
                if (c1 > r0) sacc[nt][1] = -1e30f;
                if (c0 > r1) sacc[nt][2] = -1e30f;
                if (c1 > r1) sacc[nt][3] = -1e30f;
            }
        }

        // ---- online softmax (log2 units) ----
        float rm0 = -1e30f, rm1 = -1e30f;
#pragma unroll
        for (int nt = 0; nt < 8; ++nt) {
            rm0 = fmaxf(rm0, fmaxf(sacc[nt][0], sacc[nt][1]));
            rm1 = fmaxf(rm1, fmaxf(sacc[nt][2], sacc[nt][3]));
        }
        rm0 = fmaxf(rm0, __shfl_xor_sync(0xffffffffu, rm0, 1));
        rm0 = fmaxf(rm0, __shfl_xor_sync(0xffffffffu, rm0, 2));
        rm1 = fmaxf(rm1, __shfl_xor_sync(0xffffffffu, rm1, 1));
        rm1 = fmaxf(rm1, __shfl_xor_sync(0xffffffffu, rm1, 2));
        float mn0 = fmaxf(m0, rm0), mn1 = fmaxf(m1, rm1);
        float corr0 = exp2f(m0 - mn0), corr1 = exp2f(m1 - mn1);
        m0 = mn0; m1 = mn1;

        float rs0 = 0.f, rs1 = 0.f;
#pragma unroll
        for (int nt = 0; nt < 8; ++nt) {
            float p00 = exp2f(sacc[nt][0] - mn0);
            float p01 = exp2f(sacc[nt][1] - mn0);
            float p10 = exp2f(sacc[nt][2] - mn1);
            float p11 = exp2f(sacc[nt][3] - mn1);
            rs0 += p00 + p01;
            rs1 += p10 + p11;
            *(uint32_t*)&Ps[(wm + g)*FP_STR + 8*nt + 2*tig]     = h2u(p00, p01);
            *(uint32_t*)&Ps[(wm + g + 8)*FP_STR + 8*nt + 2*tig] = h2u(p10, p11);
        }
        rs0 += __shfl_xor_sync(0xffffffffu, rs0, 1);
        rs0 += __shfl_xor_sync(0xffffffffu, rs0, 2);
        rs1 += __shfl_xor_sync(0xffffffffu, rs1, 1);
        rs1 += __shfl_xor_sync(0xffffffffu, rs1, 2);
        l0 = l0*corr0 + rs0;
        l1 = l1*corr1 + rs1;
        if (tig == 0) { cs[wm + g] = corr0; cs[wm + g + 8] = corr1; }
        __syncthreads();

        // ---- rescale O then O += P V (warps 4m x 2n) ----
#pragma unroll
        for (int mt = 0; mt < 2; ++mt) {
            int rb = 32*pm + 16*mt;
            float c0 = cs[rb + g], c1 = cs[rb + g + 8];
#pragma unroll
            for (int nt = 0; nt < 8; ++nt) {
                o[mt][nt][0] *= c0; o[mt][nt][1] *= c0;
                o[mt][nt][2] *= c1; o[mt][nt][3] *= c1;
            }
        }
#pragma unroll
        for (int ks = 0; ks < 4; ++ks) {
            int kk = (ks << 4) + (tig << 1);
            uint32_t a[2][4];
#pragma unroll
            for (int mt = 0; mt < 2; ++mt) {
                int rb = 32*pm + 16*mt;
                a[mt][0] = *(const uint32_t*)&Ps[(rb + g)*FP_STR + kk];
                a[mt][1] = *(const uint32_t*)&Ps[(rb + g + 8)*FP_STR + kk];
                a[mt][2] = *(const uint32_t*)&Ps[(rb + g)*FP_STR + kk + 8];
                a[mt][3] = *(const uint32_t*)&Ps[(rb + g + 8)*FP_STR + kk + 8];
            }
#pragma unroll
            for (int nt = 0; nt < 8; ++nt) {
                uint32_t b0 = *(const uint32_t*)&Vt[(64*pn + 8*nt + g)*FV_STR + kk];
                uint32_t b1 = *(const uint32_t*)&Vt[(64*pn + 8*nt + g)*FV_STR + kk + 8];
                mma_f16(o[0][nt], a[0], b0, b1);
                mma_f16(o[1][nt], a[1], b0, b1);
            }
        }
        __syncthreads();
    }

    // publish l, then divide + store fp16 attn
    float* ls = cs;
    if (tig == 0) { ls[wm + g] = l0; ls[wm + g + 8] = l1; }
    __syncthreads();

#pragma unroll
    for (int mt = 0; mt < 2; ++mt) {
        int rb = 32*pm + 16*mt;
        float inv0 = 1.f / ls[rb + g];
        float inv1 = 1.f / ls[rb + g + 8];
        int gr0 = q0 + rb + g, gr1 = gr0 + 8;
#pragma unroll
        for (int nt = 0; nt < 8; ++nt) {
            int dcol = 64*pn + 8*nt + 2*tig;
            *(uint32_t*)(attn + ((size_t)(b*T_ + gr0))*D_ + h*HD_ + dcol) =
                h2u(o[mt][nt][0]*inv0, o[mt][nt][1]*inv0);
            *(uint32_t*)(attn + ((size_t)(b*T_ + gr1))*D_ + h*HD_ + dcol) =
                h2u(o[mt][nt][2]*inv1, o[mt][nt][3]*inv1);
        }
    }
}

// ---------------- launch ----------------
extern "C" void kernel_launch(void* const* d_in, const int* in_sizes, int n_in,
                              void* d_out, int out_size) {
    const float* x  = (const float*)d_in[0];
    const float* Wq = (const float*)d_in[1];
    const float* Wk = (const float*)d_in[2];
    const float* Wv = (const float*)d_in[3];
    const float* Wo = (const float*)d_in[4];
    float* out = (float*)d_out;

    float *qkv;
    __half *xh, *wcatT, *worT, *qr, *kr, *vT, *attn;
    cudaGetSymbolAddress((void**)&qkv,   g_qkv);
    cudaGetSymbolAddress((void**)&xh,    g_xh);
    cudaGetSymbolAddress((void**)&wcatT, g_wcatT);
    cudaGetSymbolAddress((void**)&worT,  g_worT);
    cudaGetSymbolAddress((void**)&qr,    g_qr);
    cudaGetSymbolAddress((void**)&kr,    g_kr);
    cudaGetSymbolAddress((void**)&vT,    g_vT);
    cudaGetSymbolAddress((void**)&attn,  g_attn);

    rope_table_kernel<<<T_, 64>>>();

    // fp16 conversion of x; transpose+fp16 weights (K-major B operands)
    int n4x = MROWS*D_/4;
    conv_half<<<(n4x + 255)/256, 256>>>((const float4*)x, (__half2*)xh, n4x);
    trans_half<<<dim3(D_/32,   D_/32), 256>>>(Wq, wcatT,                   D_,   D_);
    trans_half<<<dim3(DKV_/32, D_/32), 256>>>(Wk, wcatT + (size_t)2048*D_, DKV_, D_);
    trans_half<<<dim3(DKV_/32, D_/32), 256>>>(Wv, wcatT + (size_t)2560*D_, DKV_, D_);
    trans_half<<<dim3(D_/32,   D_/32), 256>>>(Wo, worT,                    D_,   D_);

    // fused QKV projection (fp16 tensor cores)
    cudaFuncSetAttribute(gemm_f16, cudaFuncAttributeMaxDynamicSharedMemorySize, GM_SMEM);
    gemm_f16<<<dim3(NQKV/128, MROWS/128), 256, GM_SMEM>>>(xh, wcatT, qkv,
                                                          MROWS, NQKV, D_, NQKV);

    // RoPE (+scale*log2e fold for Q) and V transpose -> fp16 operand layouts
    rope_round_h<<<dim3(T_, H_,   B_), 128>>>(qkv, qr, H_,   0,    QSCALE);
    rope_round_h<<<dim3(T_, HKV_, B_), 128>>>(qkv, kr, HKV_, 2048, 1.0f);
    vtrans_h<<<dim3(T_/32, 16, B_), 256>>>(qkv, vT);

    // fp16 flash attention
    cudaFuncSetAttribute(flash_f16, cudaFuncAttributeMaxDynamicSharedMemorySize, FSM_BYTES);
    flash_f16<<<dim3(T_/128, B_*H_), 256, FSM_BYTES>>>(qr, kr, vT, attn);

    // output projection (fp16 tensor cores, f32 out)
    gemm_f16<<<dim3(D_/128, MROWS/128), 256, GM_SMEM>>>(attn, worT, out,
                                                        MROWS, D_, D_, D_);
}

// round 6
// speedup vs baseline: 5.9653x; 1.0882x over previous
#include <cuda_runtime.h>
#include <cuda_fp16.h>
#include <math.h>
#include <stdint.h>

// ---------------- problem constants ----------------
#define B_   2
#define T_   2048
#define D_   2048
#define H_   16
#define HKV_ 4
#define HD_  128
#define DKV_ (HKV_*HD_)    // 512
#define NQKV 3072          // fused q|k|v projection width
#define MROWS (B_*T_)      // 4096
#define QSCALE ((float)(1.4426950408889634 * 0.08838834764831845))

// ---------------- scratch (device globals) ----------------
__device__ __align__(16) __half g_xh   [(size_t)MROWS * D_];    // x in fp16
__device__ __align__(16) __half g_wcatT[(size_t)NQKV * D_];     // [Wq|Wk|Wv]^T fp16: [n][k]
__device__ __align__(16) __half g_worT [(size_t)D_ * D_];       // Wo^T fp16: [n][k]
__device__ __align__(16) __half g_qr   [(size_t)B_*H_*T_*HD_];  // Q roped, (bh,t,d)
__device__ __align__(16) __half g_kr   [(size_t)B_*HKV_*T_*HD_];// K roped
__device__ __align__(16) __half g_vT   [(size_t)B_*HKV_*HD_*T_];// V^T, (bkh,d,t)
__device__ __align__(16) __half g_attn [(size_t)MROWS * D_];    // attention out fp16
__device__ float g_cos_t[T_*64];
__device__ float g_sin_t[T_*64];

// ---------------- helpers ----------------
__device__ __forceinline__ uint32_t smem_u32(const void* p) {
    return (uint32_t)__cvta_generic_to_shared(p);
}
__device__ __forceinline__ void cp_async16(uint32_t dst, const void* src) {
    asm volatile("cp.async.cg.shared.global [%0], [%1], 16;\n" :: "r"(dst), "l"(src));
}
__device__ __forceinline__ void mma_f16(float* c, const uint32_t* a, uint32_t b0, uint32_t b1) {
    asm volatile(
        "mma.sync.aligned.m16n8k16.row.col.f32.f16.f16.f32 "
        "{%0,%1,%2,%3}, {%4,%5,%6,%7}, {%8,%9}, {%0,%1,%2,%3};\n"
        : "+f"(c[0]), "+f"(c[1]), "+f"(c[2]), "+f"(c[3])
        : "r"(a[0]), "r"(a[1]), "r"(a[2]), "r"(a[3]), "r"(b0), "r"(b1));
}
__device__ __forceinline__ uint32_t h2u(float a, float b) {
    __half2 h = __floats2half2_rn(a, b);
    return *(uint32_t*)&h;
}

// ---------------- RoPE table (fp64 precompute) ----------------
__global__ void rope_table_kernel() {
    int t = blockIdx.x;
    int i = threadIdx.x;                       // 0..63
    double inv = exp(-((double)(2*i) / 128.0) * 9.210340371976182736);
    double ang = (double)t * inv;
    g_cos_t[t*64 + i] = (float)cos(ang);
    g_sin_t[t*64 + i] = (float)sin(ang);
}

// ---------------- f32 -> fp16 conversion ----------------
__global__ void conv_half(const float4* __restrict__ in, __half2* __restrict__ out, int n4) {
    int i = blockIdx.x * blockDim.x + threadIdx.x;
    if (i < n4) {
        float4 v = in[i];
        out[2*i]     = __floats2half2_rn(v.x, v.y);
        out[2*i + 1] = __floats2half2_rn(v.z, v.w);
    }
}

// ---------------- transpose + fp16:  out[n][k] = h(in[k][n]) ----------------
__global__ void trans_half(const float* __restrict__ in, __half* __restrict__ out,
                           int cols, int ostride) {
    __shared__ float S[32][33];
    int k0 = blockIdx.y << 5;
    int n0 = blockIdx.x << 5;
    for (int e = threadIdx.x; e < 1024; e += 256) {
        int r = e >> 5, c = e & 31;
        S[r][c] = in[(size_t)(k0 + r)*cols + n0 + c];
    }
    __syncthreads();
    for (int e = threadIdx.x; e < 1024; e += 256) {
        int r = e >> 5, c = e & 31;
        out[(size_t)(n0 + r)*ostride + k0 + c] = __float2half_rn(S[c][r]);
    }
}

// ---------------- shared GEMM tile loader ----------------
#define BKH 32
#define ASTR 40                                  // padded row stride (halfs)
#define STG_HALFS (2*128*ASTR)                   // A tile + B tile per stage
#define GM_SMEM   (3*STG_HALFS*2)                // bytes (61440)

__device__ __forceinline__ void gemm_issue(const __half* __restrict__ Ag,
                                           const __half* __restrict__ Bg,
                                           uint32_t sbase, int K, int tid) {
    uint32_t sB = sbase + 128*ASTR*2;
#pragma unroll
    for (int i = 0; i < 2; ++i) {
        int c = tid + (i << 8);
        int r = c >> 2, cb = (c & 3) << 3;
        cp_async16(sbase + (r*ASTR + cb)*2, Ag + (size_t)r*K + cb);
    }
#pragma unroll
    for (int i = 0; i < 2; ++i) {
        int c = tid + (i << 8);
        int r = c >> 2, cb = (c & 3) << 3;
        cp_async16(sB + (r*ASTR + cb)*2, Bg + (size_t)r*K + cb);
    }
    asm volatile("cp.async.commit_group;\n");
}

// ---------------- plain fp16 GEMM (used for Wo): C f32 = A @ Bt^T ----------------
__global__ __launch_bounds__(256, 2)
void gemm_f16(const __half* __restrict__ A, const __half* __restrict__ Bt,
              float* __restrict__ C, int K, int ldc) {
    extern __shared__ __half smh[];
    uint32_t sbase = smem_u32(smh);
    int tid  = threadIdx.x;
    int lane = tid & 31, wid = tid >> 5;
    int g = lane >> 2, tig = lane & 3;
    int wm = (wid >> 1) << 5;
    int wn = (wid & 1) << 6;
    int row0 = blockIdx.y << 7;
    int col0 = blockIdx.x << 7;

    const __half* Abase = A  + (size_t)row0 * K;
    const __half* Bbase = Bt + (size_t)col0 * K;

    float acc[2][8][4];
#pragma unroll
    for (int mt = 0; mt < 2; ++mt)
#pragma unroll
        for (int nt = 0; nt < 8; ++nt)
#pragma unroll
            for (int r = 0; r < 4; ++r) acc[mt][nt][r] = 0.f;

    int iters = K / BKH;
    gemm_issue(Abase,       Bbase,       sbase,               K, tid);
    gemm_issue(Abase + BKH, Bbase + BKH, sbase + STG_HALFS*2, K, tid);

    for (int it = 0; it < iters; ++it) {
        if (it + 2 < iters) {
            asm volatile("cp.async.wait_group %0;\n" :: "n"(1));
        } else {
            asm volatile("cp.async.wait_group %0;\n" :: "n"(0));
        }
        __syncthreads();
        if (it + 2 < iters)
            gemm_issue(Abase + (it+2)*BKH, Bbase + (it+2)*BKH,
                       sbase + ((it+2) % 3)*STG_HALFS*2, K, tid);

        const __half* As = smh + (it % 3)*STG_HALFS;
        const __half* Bs = As + 128*ASTR;
#pragma unroll
        for (int ks = 0; ks < 2; ++ks) {
            int kk = (ks << 4) + (tig << 1);
            uint32_t a[2][4], b[8][2];
#pragma unroll
            for (int mt = 0; mt < 2; ++mt) {
                int r = wm + (mt << 4) + g;
                a[mt][0] = *(const uint32_t*)&As[ r     *ASTR + kk];
                a[mt][1] = *(const uint32_t*)&As[(r + 8)*ASTR + kk];
                a[mt][2] = *(const uint32_t*)&As[ r     *ASTR + kk + 8];
                a[mt][3] = *(const uint32_t*)&As[(r + 8)*ASTR + kk + 8];
            }
#pragma unroll
            for (int nt = 0; nt < 8; ++nt) {
                int n = wn + (nt << 3) + g;
                b[nt][0] = *(const uint32_t*)&Bs[n*ASTR + kk];
                b[nt][1] = *(const uint32_t*)&Bs[n*ASTR + kk + 8];
            }
#pragma unroll
            for (int mt = 0; mt < 2; ++mt)
#pragma unroll
                for (int nt = 0; nt < 8; ++nt)
                    mma_f16(acc[mt][nt], a[mt], b[nt][0], b[nt][1]);
        }
        __syncthreads();
    }

#pragma unroll
    for (int mt = 0; mt < 2; ++mt) {
#pragma unroll
        for (int nt = 0; nt < 8; ++nt) {
            int r    = row0 + wm + (mt << 4) + g;
            int ccol = col0 + wn + (nt << 3) + (tig << 1);
            *(float2*)(C + (size_t)r*ldc + ccol)       = make_float2(acc[mt][nt][0], acc[mt][nt][1]);
            *(float2*)(C + (size_t)(r + 8)*ldc + ccol) = make_float2(acc[mt][nt][2], acc[mt][nt][3]);
        }
    }
}

// ---------------- QKV GEMM with fused RoPE/layout epilogue ----------------
// Warp n-tiling: n-base = 8*(wid&1) + 16*nt  ->  RoPE pair cols (d, d+64) are
// (nt, nt+4) IN THE SAME THREAD: rotate in f32 registers, round once to fp16.
// head = blockIdx.x: 0-15 -> Q (rope+scale), 16-19 -> K (rope), 20-23 -> V (smem transpose).
__global__ __launch_bounds__(256, 2)
void gemm_qkv(const __half* __restrict__ A, const __half* __restrict__ Bt,
              __half* __restrict__ qrOut, __half* __restrict__ krOut,
              __half* __restrict__ vtOut) {
    extern __shared__ __half smh[];
    uint32_t sbase = smem_u32(smh);
    const int K = D_;
    int tid  = threadIdx.x;
    int lane = tid & 31, wid = tid >> 5;
    int g = lane >> 2, tig = lane & 3;
    int wm = (wid >> 1) << 5;
    int wn8 = (wid & 1) << 3;
    int row0 = blockIdx.y << 7;
    int col0 = blockIdx.x << 7;

    const __half* Abase = A  + (size_t)row0 * K;
    const __half* Bbase = Bt + (size_t)col0 * K;

    float acc[2][8][4];
#pragma unroll
    for (int mt = 0; mt < 2; ++mt)
#pragma unroll
        for (int nt = 0; nt < 8; ++nt)
#pragma unroll
            for (int r = 0; r < 4; ++r) acc[mt][nt][r] = 0.f;

    int iters = K / BKH;
    gemm_issue(Abase,       Bbase,       sbase,               K, tid);
    gemm_issue(Abase + BKH, Bbase + BKH, sbase + STG_HALFS*2, K, tid);

    for (int it = 0; it < iters; ++it) {
        if (it + 2 < iters) {
            asm volatile("cp.async.wait_group %0;\n" :: "n"(1));
        } else {
            asm volatile("cp.async.wait_group %0;\n" :: "n"(0));
        }
        __syncthreads();
        if (it + 2 < iters)
            gemm_issue(Abase + (it+2)*BKH, Bbase + (it+2)*BKH,
                       sbase + ((it+2) % 3)*STG_HALFS*2, K, tid);

        const __half* As = smh + (it % 3)*STG_HALFS;
        const __half* Bs = As + 128*ASTR;
#pragma unroll
        for (int ks = 0; ks < 2; ++ks) {
            int kk = (ks << 4) + (tig << 1);
            uint32_t a[2][4], b[8][2];
#pragma unroll
            for (int mt = 0; mt < 2; ++mt) {
                int r = wm + (mt << 4) + g;
                a[mt][0] = *(const uint32_t*)&As[ r     *ASTR + kk];
                a[mt][1] = *(const uint32_t*)&As[(r + 8)*ASTR + kk];
                a[mt][2] = *(const uint32_t*)&As[ r     *ASTR + kk + 8];
                a[mt][3] = *(const uint32_t*)&As[(r + 8)*ASTR + kk + 8];
            }
#pragma unroll
            for (int nt = 0; nt < 8; ++nt) {
                int n = wn8 + (nt << 4) + g;       // interleaved n-tiling
                b[nt][0] = *(const uint32_t*)&Bs[n*ASTR + kk];
                b[nt][1] = *(const uint32_t*)&Bs[n*ASTR + kk + 8];
            }
#pragma unroll
            for (int mt = 0; mt < 2; ++mt)
#pragma unroll
                for (int nt = 0; nt < 8; ++nt)
                    mma_f16(acc[mt][nt], a[mt], b[nt][0], b[nt][1]);
        }
        __syncthreads();
    }

    // -------- fused epilogue --------
    int head  = blockIdx.x;             // tile width 128 == one head
    int trow0 = row0 & (T_ - 1);
    int bb    = row0 >> 11;

    if (head < 20) {
        // Q or K: RoPE fully in registers (pairs are nt and nt+4)
        float scale = (head < 16) ? QSCALE : 1.0f;
        __half* obase = (head < 16)
            ? qrOut + ((size_t)(bb*H_   + head     )*T_ + trow0)*HD_
            : krOut + ((size_t)(bb*HKV_ + head - 16)*T_ + trow0)*HD_;
#pragma unroll
        for (int mt = 0; mt < 2; ++mt) {
#pragma unroll
            for (int rh = 0; rh < 2; ++rh) {
                int r = wm + (mt << 4) + g + (rh << 3);   // tile-local row
                int t = trow0 + r;
                int i0 = rh << 1;                          // acc idx 0/1 or 2/3
#pragma unroll
                for (int nt = 0; nt < 4; ++nt) {
                    int dm = wn8 + (nt << 4) + (tig << 1); // 0..62 (even)
                    float2 cv = *(const float2*)&g_cos_t[t*64 + dm];
                    float2 sv = *(const float2*)&g_sin_t[t*64 + dm];
                    float a0 = acc[mt][nt][i0],     a1 = acc[mt][nt][i0+1];
                    float b0 = acc[mt][nt+4][i0],   b1 = acc[mt][nt+4][i0+1];
                    uint32_t lo = h2u((a0*cv.x - b0*sv.x)*scale,
                                      (a1*cv.y - b1*sv.y)*scale);
                    uint32_t hi = h2u((b0*cv.x + a0*sv.x)*scale,
                                      (b1*cv.y + a1*sv.y)*scale);
                    *(uint32_t*)&obase[(size_t)r*HD_ + dm]      = lo;
                    *(uint32_t*)&obase[(size_t)r*HD_ + dm + 64] = hi;
                }
            }
        }
    } else {
        // V: transpose through smem (stride 132 halfs), write (bkh, d, t)
        __half* S2 = smh;                 // 128*132*2 = 33792 B <= 61440
#pragma unroll
        for (int mt = 0; mt < 2; ++mt)
#pragma unroll
            for (int nt = 0; nt < 8; ++nt) {
                int r = wm + (mt << 4) + g;
                int c = wn8 + (nt << 4) + (tig << 1);
                S2[(c    )*132 + r    ] = __float2half_rn(acc[mt][nt][0]);
                S2[(c + 1)*132 + r    ] = __float2half_rn(acc[mt][nt][1]);
                S2[(c    )*132 + r + 8] = __float2half_rn(acc[mt][nt][2]);
                S2[(c + 1)*132 + r + 8] = __float2half_rn(acc[mt][nt][3]);
            }
        __syncthreads();
        __half* obase = vtOut + ((size_t)(bb*HKV_ + head - 20)*HD_)*T_ + trow0;
#pragma unroll
        for (int d = wid; d < 128; d += 8) {
            uint32_t w0 = *(uint32_t*)&S2[d*132 + 2*lane];
            uint32_t w1 = *(uint32_t*)&S2[d*132 + 64 + 2*lane];
            *(uint32_t*)&obase[(size_t)d*T_ + 2*lane]      = w0;
            *(uint32_t*)&obase[(size_t)d*T_ + 64 + 2*lane] = w1;
        }
    }
}

// ---------------- fp16 flash attention, register-resident P ----------------
// Q tile 128, K/V tile 64, hd=128. 8 warps, warp w owns rows 16w..16w+15
// through BOTH phases; S C-frags repack into PV A-frags in registers.
// One __syncthreads per k-tile; K/V double buffered via cp.async.
#define FK_STR 136
#define FV_STR 72
#define FKS0 0
#define FKS1 (64*FK_STR)                  // 8704
#define FVT0 (2*64*FK_STR)                // 17408
#define FVT1 (FVT0 + 128*FV_STR)          // 26624
#define FSM_BYTES ((FVT0 + 2*128*FV_STR)*2)   // 71680

__device__ __forceinline__ void fa_issue(const __half* __restrict__ kbase,
                                         const __half* __restrict__ vbase,
                                         uint32_t sbase, int buf, int k0, int tid) {
    uint32_t ks = sbase + (buf ? FKS1 : FKS0)*2;
    uint32_t vt = sbase + (buf ? FVT1 : FVT0)*2;
#pragma unroll
    for (int i = 0; i < 4; ++i) {                 // K: 64 rows x 16 chunks
        int c = tid + (i << 8);
        int row = c >> 4, cb = (c & 15) << 3;
        cp_async16(ks + (row*FK_STR + cb)*2, kbase + (size_t)(k0 + row)*HD_ + cb);
    }
#pragma unroll
    for (int i = 0; i < 4; ++i) {                 // V^T: 128 d-rows x 8 chunks
        int c = tid + (i << 8);
        int d = c >> 3, cb = (c & 7) << 3;
        cp_async16(vt + (d*FV_STR + cb)*2, vbase + (size_t)d*T_ + k0 + cb);
    }
    asm volatile("cp.async.commit_group;\n");
}

__global__ __launch_bounds__(256, 1)
void flash_f16(const __half* __restrict__ qr, const __half* __restrict__ kr,
               const __half* __restrict__ vT, __half* __restrict__ attn) {
    extern __shared__ __half smh[];
    uint32_t sbase = smem_u32(smh);

    int tid = threadIdx.x, lane = tid & 31, wid = tid >> 5;
    int g = lane >> 2, tig = lane & 3;
    int qi = gridDim.x - 1 - blockIdx.x;          // heavy tiles first
    int q0 = qi << 7;
    int bh = blockIdx.y;
    int b = bh >> 4, h = bh & 15, kvh = h >> 2;
    int nkt = 2*qi + 2;

    const __half* qbase = qr + ((size_t)bh * T_) * HD_;
    const __half* kbase = kr + ((size_t)(b*HKV_ + kvh) * T_) * HD_;
    const __half* vbase = vT + ((size_t)(b*HKV_ + kvh) * HD_) * T_;

    fa_issue(kbase, vbase, sbase, 0, 0, tid);

    // preload Q fragments (warp rows wm..wm+15): 8 ksteps x 4 regs
    int wm = wid << 4;
    uint32_t qf[8][4];
    {
        const __half* r0p = qbase + (size_t)(q0 + wm + g)*HD_;
        const __half* r1p = qbase + (size_t)(q0 + wm + g + 8)*HD_;
#pragma unroll
        for (int ks = 0; ks < 8; ++ks) {
            int kk = (ks << 4) + (tig << 1);
            qf[ks][0] = __ldg((const uint32_t*)(r0p + kk));
            qf[ks][1] = __ldg((const uint32_t*)(r1p + kk));
            qf[ks][2] = __ldg((const uint32_t*)(r0p + kk + 8));
            qf[ks][3] = __ldg((const uint32_t*)(r1p + kk + 8));
        }
    }

    float o[16][4];                                // n = full hd 128 (16 x n8)
#pragma unroll
    for (int nt = 0; nt < 16; ++nt)
#pragma unroll
        for (int r = 0; r < 4; ++r) o[nt][r] = 0.f;
    float m0 = -1e30f, m1 = -1e30f, l0 = 0.f, l1 = 0.f;

    for (int kt = 0; kt < nkt; ++kt) {
        asm volatile("cp.async.wait_group 0;\n");
        __syncthreads();                           // buf[kt&1] visible; all reads of
                                                   // buf[(kt+1)&1] from kt-1 done
        if (kt + 1 < nkt)
            fa_issue(kbase, vbase, sbase, (kt+1) & 1, (kt+1) << 6, tid);

        const __half* Ks = smh + ((kt & 1) ? FKS1 : FKS0);
        const __half* Vt = smh + ((kt & 1) ? FVT1 : FVT0);

        // ---- S = Q K^T ----
        float sacc[8][4];
#pragma unroll
        for (int nt = 0; nt < 8; ++nt)
#pragma unroll
            for (int r = 0; r < 4; ++r) sacc[nt][r] = 0.f;
#pragma unroll
        for (int ks = 0; ks < 8; ++ks) {
            int kk = (ks << 4) + (tig << 1);
#pragma unroll
            for (int nt = 0; nt < 8; ++nt) {
                uint32_t b0 = *(const uint32_t*)&Ks[(8*nt + g)*FK_STR + kk];
                uint32_t b1 = *(const uint32_t*)&Ks[(8*nt + g)*FK_STR + kk + 8];
                mma_f16(sacc[nt], qf[ks], b0, b1);
            }
        }

        // ---- causal mask on the two diagonal k-tiles ----
        if (kt >= nkt - 2) {
            int k0 = kt << 6;
            int r0 = q0 + wm + g, r1 = r0 + 8;
#pragma unroll
            for (int nt = 0; nt < 8; ++nt) {
                int c0 = k0 + 8*nt + 2*tig, c1 = c0 + 1;
                if (c0 > r0) sacc[nt][0] = -1e30f;
                if (c1 > r0) sacc[nt][1] = -1e30f;
                if (c0 > r1) sacc[nt][2] = -1e30f;
                if (c1 > r1) sacc[nt][3] = -1e30f;
            }
        }

        // ---- online softmax (log2 units; quad-local reductions) ----
        float rm0 = -1e30f, rm1 = -1e30f;
#pragma unroll
        for (int nt = 0; nt < 8; ++nt) {
            rm0 = fmaxf(rm0, fmaxf(sacc[nt][0], sacc[nt][1]));
            rm1 = fmaxf(rm1, fmaxf(sacc[nt][2], sacc[nt][3]));
        }
        rm0 = fmaxf(rm0, __shfl_xor_sync(0xffffffffu, rm0, 1));
        rm0 = fmaxf(rm0, __shfl_xor_sync(0xffffffffu, rm0, 2));
        rm1 = fmaxf(rm1, __shfl_xor_sync(0xffffffffu, rm1, 1));
        rm1 = fmaxf(rm1, __shfl_xor_sync(0xffffffffu, rm1, 2));
        float mn0 = fmaxf(m0, rm0), mn1 = fmaxf(m1, rm1);
        float corr0 = exp2f(m0 - mn0), corr1 = exp2f(m1 - mn1);
        m0 = mn0; m1 = mn1;

        float rs0 = 0.f, rs1 = 0.f;
#pragma unroll
        for (int nt = 0; nt < 8; ++nt) {
            sacc[nt][0] = exp2f(sacc[nt][0] - mn0);
            sacc[nt][1] = exp2f(sacc[nt][1] - mn0);
            sacc[nt][2] = exp2f(sacc[nt][2] - mn1);
            sacc[nt][3] = exp2f(sacc[nt][3] - mn1);
            rs0 += sacc[nt][0] + sacc[nt][1];
            rs1 += sacc[nt][2] + sacc[nt][3];
        }
        rs0 += __shfl_xor_sync(0xffffffffu, rs0, 1);
        rs0 += __shfl_xor_sync(0xffffffffu, rs0, 2);
        rs1 += __shfl_xor_sync(0xffffffffu, rs1, 1);
        rs1 += __shfl_xor_sync(0xffffffffu, rs1, 2);
        l0 = l0*corr0 + rs0;
        l1 = l1*corr1 + rs1;

        // ---- pack P into PV A-fragments (pure register repack) ----
        uint32_t pf[4][4];
#pragma unroll
        for (int ks2 = 0; ks2 < 4; ++ks2) {
            pf[ks2][0] = h2u(sacc[2*ks2  ][0], sacc[2*ks2  ][1]);
            pf[ks2][1] = h2u(sacc[2*ks2  ][2], sacc[2*ks2  ][3]);
            pf[ks2][2] = h2u(sacc[2*ks2+1][0], sacc[2*ks2+1][1]);
            pf[ks2][3] = h2u(sacc[2*ks2+1][2], sacc[2*ks2+1][3]);
        }

        // ---- rescale O, then O += P V ----
#pragma unroll
        for (int nt = 0; nt < 16; ++nt) {
            o[nt][0] *= corr0; o[nt][1] *= corr0;
            o[nt][2] *= corr1; o[nt][3] *= corr1;
        }
#pragma unroll
        for (int ks2 = 0; ks2 < 4; ++ks2) {
            int kk = (ks2 << 4) + (tig << 1);
#pragma unroll
            for (int nt = 0; nt < 16; ++nt) {
                uint32_t b0 = *(const uint32_t*)&Vt[(8*nt + g)*FV_STR + kk];
                uint32_t b1 = *(const uint32_t*)&Vt[(8*nt + g)*FV_STR + kk + 8];
                mma_f16(o[nt], pf[ks2], b0, b1);
            }
        }
    }

    // ---- epilogue: divide by l, store fp16 ----
    float inv0 = 1.f / l0, inv1 = 1.f / l1;
    int gr0 = q0 + wm + g, gr1 = gr0 + 8;
    __half* ob0 = attn + ((size_t)(b*T_ + gr0))*D_ + h*HD_;
    __half* ob1 = attn + ((size_t)(b*T_ + gr1))*D_ + h*HD_;
#pragma unroll
    for (int nt = 0; nt < 16; ++nt) {
        int dcol = 8*nt + 2*tig;
        *(uint32_t*)(ob0 + dcol) = h2u(o[nt][0]*inv0, o[nt][1]*inv0);
        *(uint32_t*)(ob1 + dcol) = h2u(o[nt][2]*inv1, o[nt][3]*inv1);
    }
}

// ---------------- launch ----------------
extern "C" void kernel_launch(void* const* d_in, const int* in_sizes, int n_in,
                              void* d_out, int out_size) {
    const float* x  = (const float*)d_in[0];
    const float* Wq = (const float*)d_in[1];
    const float* Wk = (const float*)d_in[2];
    const float* Wv = (const float*)d_in[3];
    const float* Wo = (const float*)d_in[4];
    float* out = (float*)d_out;

    __half *xh, *wcatT, *worT, *qr, *kr, *vT, *attn;
    cudaGetSymbolAddress((void**)&xh,    g_xh);
    cudaGetSymbolAddress((void**)&wcatT, g_wcatT);
    cudaGetSymbolAddress((void**)&worT,  g_worT);
    cudaGetSymbolAddress((void**)&qr,    g_qr);
    cudaGetSymbolAddress((void**)&kr,    g_kr);
    cudaGetSymbolAddress((void**)&vT,    g_vT);
    cudaGetSymbolAddress((void**)&attn,  g_attn);

    rope_table_kernel<<<T_, 64>>>();

    // fp16 conversion of x; transpose+fp16 weights (K-major B operands)
    int n4x = MROWS*D_/4;
    conv_half<<<(n4x + 255)/256, 256>>>((const float4*)x, (__half2*)xh, n4x);
    trans_half<<<dim3(D_/32,   D_/32), 256>>>(Wq, wcatT,                   D_,   D_);
    trans_half<<<dim3(DKV_/32, D_/32), 256>>>(Wk, wcatT + (size_t)2048*D_, DKV_, D_);
    trans_half<<<dim3(DKV_/32, D_/32), 256>>>(Wv, wcatT + (size_t)2560*D_, DKV_, D_);
    trans_half<<<dim3(D_/32,   D_/32), 256>>>(Wo, worT,                    D_,   D_);

    // fused QKV projection + RoPE + layout (writes qr/kr/vT directly)
    cudaFuncSetAttribute(gemm_qkv, cudaFuncAttributeMaxDynamicSharedMemorySize, GM_SMEM);
    gemm_qkv<<<dim3(NQKV/128, MROWS/128), 256, GM_SMEM>>>(xh, wcatT, qr, kr, vT);

    // fp16 flash attention (register-resident P)
    cudaFuncSetAttribute(flash_f16, cudaFuncAttributeMaxDynamicSharedMemorySize, FSM_BYTES);
    flash_f16<<<dim3(T_/128, B_*H_), 256, FSM_BYTES>>>(qr, kr, vT, attn);

    // output projection (f32 out)
    cudaFuncSetAttribute(gemm_f16, cudaFuncAttributeMaxDynamicSharedMemorySize, GM_SMEM);
    gemm_f16<<<dim3(D_/128, MROWS/128), 256, GM_SMEM>>>(attn, worT, out, D_, D_);
}